// round 2
// baseline (speedup 1.0000x reference)
#include <cuda_runtime.h>
#include <math.h>

#define BATCH 64
#define SENC  64
#define TDEC  31          // decoder steps = T-1
#define EMB   256
#define HID   512
#define G4    2048        // 4*H
#define VOC   32000
#define NBLK  128         // persistent scan blocks (all resident: 128 < 148 SMs)
#define MROWS (BATCH * TDEC)   // 1984 rows into FC

// ---------------- scratch (device globals; no allocation) ----------------
__device__ float d_xp_enc[SENC * BATCH * G4];   // [t][b][g]
__device__ float d_xp_dec[TDEC * BATCH * G4];   // [t][b][g]
__device__ float d_hbuf[2][BATCH * HID];        // ping-pong h
__device__ float d_hseq[MROWS * HID];           // [b*31+t][h] decoder outputs
__device__ unsigned d_bar_count = 0;
__device__ unsigned d_bar_gen   = 0;

// ---------------- software grid barrier (all NBLK blocks resident) ----------------
__device__ __forceinline__ void global_barrier()
{
    __syncthreads();
    if (threadIdx.x == 0) {
        unsigned gen = *((volatile unsigned*)&d_bar_gen);
        __threadfence();
        unsigned arrived = atomicAdd(&d_bar_count, 1);
        if (arrived == NBLK - 1) {
            d_bar_count = 0;
            __threadfence();
            *((volatile unsigned*)&d_bar_gen) = gen + 1;
        } else {
            while (*((volatile unsigned*)&d_bar_gen) == gen) { __nanosleep(40); }
        }
        __threadfence();
    }
    __syncthreads();
}

__device__ __forceinline__ float sigm(float x) { return 1.0f / (1.0f + expf(-x)); }

// ---------------- xp = emb[tokens] @ Wih^T + bih + bhh ----------------
// GEMM tile 64x64, K = EMB = 256. One m-tile == one timestep (rows are the 64 batches).
// which: 0 -> write d_xp_enc, 1 -> write d_xp_dec
__global__ __launch_bounds__(256) void xp_gemm_kernel(
    const int*   __restrict__ tokens, int tok_stride,
    const float* __restrict__ emb,
    const float* __restrict__ Wih,
    const float* __restrict__ bih,
    const float* __restrict__ bhh,
    int which)
{
    __shared__ float As[16][68];
    __shared__ float Bs[16][68];

    float* __restrict__ xp = which ? d_xp_dec : d_xp_enc;

    const int tid = threadIdx.x;
    const int n0  = blockIdx.x * 64;
    const int t   = blockIdx.y;          // timestep for this m-tile
    const int m0  = t * 64;

    const int lr  = tid >> 2;            // 0..63 (row within tile == batch b)
    const int lk4 = (tid & 3) * 4;       // 0,4,8,12

    const int tok = tokens[lr * tok_stride + t];
    const float* arow = emb + (size_t)tok * EMB;
    const float* brow = Wih + (size_t)(n0 + lr) * EMB;

    const int tm = (tid >> 4) * 4;
    const int tn = (tid & 15) * 4;

    float acc[4][4];
#pragma unroll
    for (int i = 0; i < 4; i++)
#pragma unroll
        for (int j = 0; j < 4; j++) acc[i][j] = 0.0f;

    for (int kc = 0; kc < EMB; kc += 16) {
        float4 av = *(const float4*)(arow + kc + lk4);
        float4 bv = *(const float4*)(brow + kc + lk4);
        __syncthreads();
        As[lk4 + 0][lr] = av.x; As[lk4 + 1][lr] = av.y;
        As[lk4 + 2][lr] = av.z; As[lk4 + 3][lr] = av.w;
        Bs[lk4 + 0][lr] = bv.x; Bs[lk4 + 1][lr] = bv.y;
        Bs[lk4 + 2][lr] = bv.z; Bs[lk4 + 3][lr] = bv.w;
        __syncthreads();
#pragma unroll
        for (int k = 0; k < 16; k++) {
            float4 a = *(const float4*)&As[k][tm];
            float4 b = *(const float4*)&Bs[k][tn];
            float af[4] = {a.x, a.y, a.z, a.w};
            float bf[4] = {b.x, b.y, b.z, b.w};
#pragma unroll
            for (int i = 0; i < 4; i++)
#pragma unroll
                for (int j = 0; j < 4; j++)
                    acc[i][j] += af[i] * bf[j];
        }
    }

#pragma unroll
    for (int j = 0; j < 4; j++) {
        int n = n0 + tn + j;
        float bsum = bih[n] + bhh[n];
#pragma unroll
        for (int i = 0; i < 4; i++) {
            int m = m0 + tm + i;
            xp[(size_t)m * G4 + n] = acc[i][j] + bsum;
        }
    }
}

// ---------------- persistent LSTM scan: 64 encoder + 31 decoder steps ----------------
// Block bid owns hidden columns j0 = bid*4 .. +3, all 64 batches.
// Thread (b, jj) computes all 4 gates for (b, j0+jj) and owns c[b][j] in a register.
__global__ __launch_bounds__(256, 1) void scan_kernel(
    const float* __restrict__ encWhh,
    const float* __restrict__ decWhh)
{
    __shared__ float ws[16][516];      // 16 Whh rows (4 gates x 4 cols), K=512 fully resident
    __shared__ float hs[2][64][20];    // h chunk double buffer, 16 k per chunk

    const int tid = threadIdx.x;
    const int bid = blockIdx.x;
    const int b   = tid >> 2;
    const int jj  = tid & 3;
    const int j0  = bid * 4;
    const int j   = j0 + jj;
    const int lk4 = jj * 4;            // 0,4,8,12 (chunk-load column offset)

    // h0 = 0 (each block zeroes exactly its own columns: 64*4 = 256 elems)
    d_hbuf[0][b * HID + j] = 0.0f;
    float c = 0.0f;

    // load encoder Whh tile into smem: row n = gate*4 + jl  ->  Whh[gate*512 + j0 + jl]
    {
        const int n    = tid >> 4;               // 0..15
        const int gate = n >> 2, jl = n & 3;
        const float* row = encWhh + (size_t)(gate * HID + j0 + jl) * HID;
        const int k4 = (tid & 15) * 4;
#pragma unroll
        for (int it = 0; it < 8; it++)
            *(float4*)&ws[n][k4 + it * 64] = *(const float4*)(row + k4 + it * 64);
    }
    __syncthreads();
    global_barrier();                  // h0 visible everywhere

    for (int step = 0; step < SENC + TDEC; step++) {
        if (step == SENC) {            // swap in decoder Whh
            __syncthreads();
            const int n    = tid >> 4;
            const int gate = n >> 2, jl = n & 3;
            const float* row = decWhh + (size_t)(gate * HID + j0 + jl) * HID;
            const int k4 = (tid & 15) * 4;
#pragma unroll
            for (int it = 0; it < 8; it++)
                *(float4*)&ws[n][k4 + it * 64] = *(const float4*)(row + k4 + it * 64);
            __syncthreads();
        }

        const float* __restrict__ hprev = d_hbuf[step & 1];
        float*       __restrict__ hnext = d_hbuf[(step & 1) ^ 1];
        const float* __restrict__ xp_t  =
            (step < SENC) ? (d_xp_enc + (size_t)step * BATCH * G4)
                          : (d_xp_dec + (size_t)(step - SENC) * BATCH * G4);

        float acc0 = 0.f, acc1 = 0.f, acc2 = 0.f, acc3 = 0.f;

        // L1 is incoherent across SMs within a launch -> h must come from L2 (__ldcg)
        float4 pv = __ldcg((const float4*)(hprev + b * HID + lk4));
        int buf = 0;
        for (int kc = 0; kc < HID; kc += 16) {
            *(float4*)&hs[buf][b][lk4] = pv;
            __syncthreads();
            if (kc + 16 < HID)
                pv = __ldcg((const float4*)(hprev + b * HID + kc + 16 + lk4));
#pragma unroll
            for (int k = 0; k < 16; k += 4) {
                float4 hv = *(const float4*)&hs[buf][b][k];
                float4 w0 = *(const float4*)&ws[0 * 4 + jj][kc + k];
                float4 w1 = *(const float4*)&ws[1 * 4 + jj][kc + k];
                float4 w2 = *(const float4*)&ws[2 * 4 + jj][kc + k];
                float4 w3 = *(const float4*)&ws[3 * 4 + jj][kc + k];
                acc0 += hv.x * w0.x; acc0 += hv.y * w0.y; acc0 += hv.z * w0.z; acc0 += hv.w * w0.w;
                acc1 += hv.x * w1.x; acc1 += hv.y * w1.y; acc1 += hv.z * w1.z; acc1 += hv.w * w1.w;
                acc2 += hv.x * w2.x; acc2 += hv.y * w2.y; acc2 += hv.z * w2.z; acc2 += hv.w * w2.w;
                acc3 += hv.x * w3.x; acc3 += hv.y * w3.y; acc3 += hv.z * w3.z; acc3 += hv.w * w3.w;
            }
            buf ^= 1;
        }

        const float* xpp = xp_t + (size_t)b * G4 + j;
        acc0 += xpp[0];
        acc1 += xpp[512];
        acc2 += xpp[1024];
        acc3 += xpp[1536];

        float ig = sigm(acc0);
        float fg = sigm(acc1);
        float gg = tanhf(acc2);
        float og = sigm(acc3);
        c = fg * c + ig * gg;
        float hn = og * tanhf(c);

        __stcg(hnext + b * HID + j, hn);
        if (step >= SENC) {
            int t = step - SENC;
            d_hseq[((size_t)b * TDEC + t) * HID + j] = hn;
        }
        global_barrier();
    }
}

// ---------------- FC: out[b][t+1][v] = hseq[b*31+t] . fc_W[v] + fc_b[v] ----------------
// 128x128 tile, K=512, 256 threads, 8x8 per thread, register-prefetch double buffer.
__global__ __launch_bounds__(256, 2) void fc_kernel(
    const float* __restrict__ W,
    const float* __restrict__ bias,
    float* __restrict__ out)
{
    __shared__ float As[2][8][132];
    __shared__ float Bs[2][8][132];

    const int tid = threadIdx.x;
    const int n0  = blockIdx.x * 128;
    const int m0  = blockIdx.y * 128;

    const int lr  = tid >> 1;           // 0..127
    const int lk4 = (tid & 1) * 4;      // 0 or 4

    int am = m0 + lr; if (am > MROWS - 1) am = MROWS - 1;
    const float* arow = d_hseq + (size_t)am * HID;
    const float* brow = W + (size_t)(n0 + lr) * HID;

    const int tm = (tid >> 4) * 8;
    const int tn = (tid & 15) * 8;

    float acc[8][8];
#pragma unroll
    for (int i = 0; i < 8; i++)
#pragma unroll
        for (int jx = 0; jx < 8; jx++) acc[i][jx] = 0.0f;

    // chunk 0
    {
        float4 av = *(const float4*)(arow + lk4);
        float4 bv = *(const float4*)(brow + lk4);
        As[0][lk4 + 0][lr] = av.x; As[0][lk4 + 1][lr] = av.y;
        As[0][lk4 + 2][lr] = av.z; As[0][lk4 + 3][lr] = av.w;
        Bs[0][lk4 + 0][lr] = bv.x; Bs[0][lk4 + 1][lr] = bv.y;
        Bs[0][lk4 + 2][lr] = bv.z; Bs[0][lk4 + 3][lr] = bv.w;
    }
    __syncthreads();

    for (int kc = 0; kc < HID / 8; kc++) {
        const int cur = kc & 1;
        float4 a2, b2;
        if (kc < HID / 8 - 1) {
            a2 = *(const float4*)(arow + (kc + 1) * 8 + lk4);
            b2 = *(const float4*)(brow + (kc + 1) * 8 + lk4);
        }
#pragma unroll
        for (int k = 0; k < 8; k++) {
            float4 aa0 = *(const float4*)&As[cur][k][tm];
            float4 aa1 = *(const float4*)&As[cur][k][tm + 4];
            float4 bb0 = *(const float4*)&Bs[cur][k][tn];
            float4 bb1 = *(const float4*)&Bs[cur][k][tn + 4];
            float af[8] = {aa0.x, aa0.y, aa0.z, aa0.w, aa1.x, aa1.y, aa1.z, aa1.w};
            float bf[8] = {bb0.x, bb0.y, bb0.z, bb0.w, bb1.x, bb1.y, bb1.z, bb1.w};
#pragma unroll
            for (int i = 0; i < 8; i++)
#pragma unroll
                for (int jx = 0; jx < 8; jx++)
                    acc[i][jx] += af[i] * bf[jx];
        }
        if (kc < HID / 8 - 1) {
            const int nx = cur ^ 1;
            As[nx][lk4 + 0][lr] = a2.x; As[nx][lk4 + 1][lr] = a2.y;
            As[nx][lk4 + 2][lr] = a2.z; As[nx][lk4 + 3][lr] = a2.w;
            Bs[nx][lk4 + 0][lr] = b2.x; Bs[nx][lk4 + 1][lr] = b2.y;
            Bs[nx][lk4 + 2][lr] = b2.z; Bs[nx][lk4 + 3][lr] = b2.w;
        }
        __syncthreads();
    }

    float bsv[8];
#pragma unroll
    for (int jx = 0; jx < 8; jx++) bsv[jx] = bias[n0 + tn + jx];

#pragma unroll
    for (int i = 0; i < 8; i++) {
        int m = m0 + tm + i;
        if (m < MROWS) {
            int bidx = m / TDEC;
            int tt   = m - bidx * TDEC;
            float* orow = out + ((size_t)bidx * 32 + tt + 1) * VOC + n0 + tn;
            float4 v0 = make_float4(acc[i][0] + bsv[0], acc[i][1] + bsv[1],
                                    acc[i][2] + bsv[2], acc[i][3] + bsv[3]);
            float4 v1 = make_float4(acc[i][4] + bsv[4], acc[i][5] + bsv[5],
                                    acc[i][6] + bsv[6], acc[i][7] + bsv[7]);
            *(float4*)(orow)     = v0;
            *(float4*)(orow + 4) = v1;
        }
    }
}

// ---------------- zero out[:, 0, :] ----------------
__global__ void zero_t0_kernel(float* __restrict__ out)
{
    int idx = blockIdx.x * blockDim.x + threadIdx.x;     // float4 granularity
    const int n4 = BATCH * (VOC / 4);
    if (idx < n4) {
        int b  = idx / (VOC / 4);
        int v4 = idx - b * (VOC / 4);
        ((float4*)(out + (size_t)b * 32 * VOC))[v4] = make_float4(0.f, 0.f, 0.f, 0.f);
    }
}

// ---------------- launch ----------------
extern "C" void kernel_launch(void* const* d_in, const int* in_sizes, int n_in,
                              void* d_out, int out_size)
{
    const int*   src     = (const int*)  d_in[0];
    const int*   tgt     = (const int*)  d_in[1];
    const float* enc_emb = (const float*)d_in[2];
    const float* dec_emb = (const float*)d_in[3];
    const float* enc_Wih = (const float*)d_in[4];
    const float* enc_Whh = (const float*)d_in[5];
    const float* enc_bih = (const float*)d_in[6];
    const float* enc_bhh = (const float*)d_in[7];
    const float* dec_Wih = (const float*)d_in[8];
    const float* dec_Whh = (const float*)d_in[9];
    const float* dec_bih = (const float*)d_in[10];
    const float* dec_bhh = (const float*)d_in[11];
    const float* fc_W    = (const float*)d_in[12];
    const float* fc_b    = (const float*)d_in[13];
    float* out = (float*)d_out;

    xp_gemm_kernel<<<dim3(G4 / 64, SENC), 256>>>(src, SENC, enc_emb, enc_Wih,
                                                 enc_bih, enc_bhh, 0);
    xp_gemm_kernel<<<dim3(G4 / 64, TDEC), 256>>>(tgt, SENC / 2 /*tgt stride = 32*/,
                                                 dec_emb, dec_Wih, dec_bih, dec_bhh, 1);
    scan_kernel<<<NBLK, 256>>>(enc_Whh, dec_Whh);
    zero_t0_kernel<<<(BATCH * (VOC / 4) + 255) / 256, 256>>>(out);
    fc_kernel<<<dim3(VOC / 128, (MROWS + 127) / 128), 256>>>(fc_W, fc_b, out);
}

// round 5
// speedup vs baseline: 1.3437x; 1.3437x over previous
#include <cuda_runtime.h>
#include <cuda_bf16.h>
#include <math.h>
#include <stdint.h>

#define BATCH 64
#define SENC  64
#define TDEC  31          // decoder steps = T-1
#define EMB   256
#define HID   512
#define G4    2048        // 4*H
#define VOC   32000
#define NBLK  128         // persistent scan blocks (all resident: 128 < 148 SMs)
#define MROWS (BATCH * TDEC)   // 1984 rows into FC
#define MPAD  2048             // padded FC rows (16 x 128)

// ---------------- scratch (device globals; no allocation) ----------------
__device__ float d_xp_enc[SENC * BATCH * G4];   // [t][b][g]
__device__ float d_xp_dec[TDEC * BATCH * G4];   // [t][b][g]
__device__ float d_hbuf[2][BATCH * HID];        // ping-pong h
__device__ float d_hseq[MROWS * HID];           // [b*31+t][h] decoder outputs
__device__ unsigned d_bar_count = 0;
__device__ unsigned d_bar_gen   = 0;

// bf16 split operands for the FC tensor-core GEMM
__device__ __nv_bfloat16 d_Ahi[MPAD * HID];
__device__ __nv_bfloat16 d_Alo[MPAD * HID];
__device__ __nv_bfloat16 d_Bhi[VOC * HID];
__device__ __nv_bfloat16 d_Blo[VOC * HID];

// ---------------- helpers ----------------
__device__ __forceinline__ uint32_t smem_u32(const void* p) {
    uint32_t a;
    asm("{ .reg .u64 t; cvta.to.shared.u64 t, %1; cvt.u32.u64 %0, t; }"
        : "=r"(a) : "l"(p));
    return a;
}
#define CP_ASYNC16(dst, src) \
    asm volatile("cp.async.cg.shared.global [%0], [%1], 16;" \
                 :: "r"(dst), "l"(src) : "memory")
#define CP_COMMIT() asm volatile("cp.async.commit_group;" ::: "memory")
#define CP_WAIT1()  asm volatile("cp.async.wait_group 1;" ::: "memory")

__device__ __forceinline__ void ldmatrix_x4(uint32_t& r0, uint32_t& r1,
                                            uint32_t& r2, uint32_t& r3, uint32_t addr)
{
    asm volatile("ldmatrix.sync.aligned.m8n8.x4.shared.b16 {%0,%1,%2,%3}, [%4];"
                 : "=r"(r0), "=r"(r1), "=r"(r2), "=r"(r3) : "r"(addr));
}
__device__ __forceinline__ void mma_16816(float* c, const uint32_t* a,
                                          uint32_t b0, uint32_t b1)
{
    asm volatile("mma.sync.aligned.m16n8k16.row.col.f32.bf16.bf16.f32 "
                 "{%0,%1,%2,%3}, {%4,%5,%6,%7}, {%8,%9}, {%0,%1,%2,%3};"
                 : "+f"(c[0]), "+f"(c[1]), "+f"(c[2]), "+f"(c[3])
                 : "r"(a[0]), "r"(a[1]), "r"(a[2]), "r"(a[3]), "r"(b0), "r"(b1));
}

// ---------------- software grid barrier (all NBLK blocks resident) ----------------
__device__ __forceinline__ void global_barrier()
{
    __syncthreads();
    if (threadIdx.x == 0) {
        unsigned gen = *((volatile unsigned*)&d_bar_gen);
        __threadfence();
        unsigned arrived = atomicAdd(&d_bar_count, 1);
        if (arrived == NBLK - 1) {
            d_bar_count = 0;
            __threadfence();
            *((volatile unsigned*)&d_bar_gen) = gen + 1;
        } else {
            while (*((volatile unsigned*)&d_bar_gen) == gen) { __nanosleep(40); }
        }
        __threadfence();
    }
    __syncthreads();
}

__device__ __forceinline__ float sigm(float x) { return 1.0f / (1.0f + expf(-x)); }

// ---------------- xp = emb[tokens] @ Wih^T + bih + bhh ----------------
__global__ __launch_bounds__(256) void xp_gemm_kernel(
    const int*   __restrict__ tokens, int tok_stride,
    const float* __restrict__ emb,
    const float* __restrict__ Wih,
    const float* __restrict__ bih,
    const float* __restrict__ bhh,
    int which)
{
    __shared__ float As[16][68];
    __shared__ float Bs[16][68];

    float* __restrict__ xp = which ? d_xp_dec : d_xp_enc;

    const int tid = threadIdx.x;
    const int n0  = blockIdx.x * 64;
    const int t   = blockIdx.y;
    const int m0  = t * 64;

    const int lr  = tid >> 2;
    const int lk4 = (tid & 3) * 4;

    const int tok = tokens[lr * tok_stride + t];
    const float* arow = emb + (size_t)tok * EMB;
    const float* brow = Wih + (size_t)(n0 + lr) * EMB;

    const int tm = (tid >> 4) * 4;
    const int tn = (tid & 15) * 4;

    float acc[4][4];
#pragma unroll
    for (int i = 0; i < 4; i++)
#pragma unroll
        for (int j = 0; j < 4; j++) acc[i][j] = 0.0f;

    for (int kc = 0; kc < EMB; kc += 16) {
        float4 av = *(const float4*)(arow + kc + lk4);
        float4 bv = *(const float4*)(brow + kc + lk4);
        __syncthreads();
        As[lk4 + 0][lr] = av.x; As[lk4 + 1][lr] = av.y;
        As[lk4 + 2][lr] = av.z; As[lk4 + 3][lr] = av.w;
        Bs[lk4 + 0][lr] = bv.x; Bs[lk4 + 1][lr] = bv.y;
        Bs[lk4 + 2][lr] = bv.z; Bs[lk4 + 3][lr] = bv.w;
        __syncthreads();
#pragma unroll
        for (int k = 0; k < 16; k++) {
            float4 a = *(const float4*)&As[k][tm];
            float4 b = *(const float4*)&Bs[k][tn];
            float af[4] = {a.x, a.y, a.z, a.w};
            float bf[4] = {b.x, b.y, b.z, b.w};
#pragma unroll
            for (int i = 0; i < 4; i++)
#pragma unroll
                for (int j = 0; j < 4; j++)
                    acc[i][j] += af[i] * bf[j];
        }
    }

#pragma unroll
    for (int j = 0; j < 4; j++) {
        int n = n0 + tn + j;
        float bsum = bih[n] + bhh[n];
#pragma unroll
        for (int i = 0; i < 4; i++) {
            int m = m0 + tm + i;
            xp[(size_t)m * G4 + n] = acc[i][j] + bsum;
        }
    }
}

// ---------------- persistent LSTM scan ----------------
__global__ __launch_bounds__(256, 1) void scan_kernel(
    const float* __restrict__ encWhh,
    const float* __restrict__ decWhh)
{
    __shared__ float ws[16][516];
    __shared__ float hs[2][64][20];

    const int tid = threadIdx.x;
    const int bid = blockIdx.x;
    const int b   = tid >> 2;
    const int jj  = tid & 3;
    const int j0  = bid * 4;
    const int j   = j0 + jj;
    const int lk4 = jj * 4;

    d_hbuf[0][b * HID + j] = 0.0f;
    float c = 0.0f;

    {
        const int n    = tid >> 4;
        const int gate = n >> 2, jl = n & 3;
        const float* row = encWhh + (size_t)(gate * HID + j0 + jl) * HID;
        const int k4 = (tid & 15) * 4;
#pragma unroll
        for (int it = 0; it < 8; it++)
            *(float4*)&ws[n][k4 + it * 64] = *(const float4*)(row + k4 + it * 64);
    }
    __syncthreads();
    global_barrier();

    for (int step = 0; step < SENC + TDEC; step++) {
        if (step == SENC) {
            __syncthreads();
            const int n    = tid >> 4;
            const int gate = n >> 2, jl = n & 3;
            const float* row = decWhh + (size_t)(gate * HID + j0 + jl) * HID;
            const int k4 = (tid & 15) * 4;
#pragma unroll
            for (int it = 0; it < 8; it++)
                *(float4*)&ws[n][k4 + it * 64] = *(const float4*)(row + k4 + it * 64);
            __syncthreads();
        }

        const float* __restrict__ hprev = d_hbuf[step & 1];
        float*       __restrict__ hnext = d_hbuf[(step & 1) ^ 1];
        const float* __restrict__ xp_t  =
            (step < SENC) ? (d_xp_enc + (size_t)step * BATCH * G4)
                          : (d_xp_dec + (size_t)(step - SENC) * BATCH * G4);

        float acc0 = 0.f, acc1 = 0.f, acc2 = 0.f, acc3 = 0.f;

        float4 pv = __ldcg((const float4*)(hprev + b * HID + lk4));
        int buf = 0;
        for (int kc = 0; kc < HID; kc += 16) {
            *(float4*)&hs[buf][b][lk4] = pv;
            __syncthreads();
            if (kc + 16 < HID)
                pv = __ldcg((const float4*)(hprev + b * HID + kc + 16 + lk4));
#pragma unroll
            for (int k = 0; k < 16; k += 4) {
                float4 hv = *(const float4*)&hs[buf][b][k];
                float4 w0 = *(const float4*)&ws[0 * 4 + jj][kc + k];
                float4 w1 = *(const float4*)&ws[1 * 4 + jj][kc + k];
                float4 w2 = *(const float4*)&ws[2 * 4 + jj][kc + k];
                float4 w3 = *(const float4*)&ws[3 * 4 + jj][kc + k];
                acc0 += hv.x * w0.x; acc0 += hv.y * w0.y; acc0 += hv.z * w0.z; acc0 += hv.w * w0.w;
                acc1 += hv.x * w1.x; acc1 += hv.y * w1.y; acc1 += hv.z * w1.z; acc1 += hv.w * w1.w;
                acc2 += hv.x * w2.x; acc2 += hv.y * w2.y; acc2 += hv.z * w2.z; acc2 += hv.w * w2.w;
                acc3 += hv.x * w3.x; acc3 += hv.y * w3.y; acc3 += hv.z * w3.z; acc3 += hv.w * w3.w;
            }
            buf ^= 1;
        }

        const float* xpp = xp_t + (size_t)b * G4 + j;
        acc0 += xpp[0];
        acc1 += xpp[512];
        acc2 += xpp[1024];
        acc3 += xpp[1536];

        float ig = sigm(acc0);
        float fg = sigm(acc1);
        float gg = tanhf(acc2);
        float og = sigm(acc3);
        c = fg * c + ig * gg;
        float hn = og * tanhf(c);

        __stcg(hnext + b * HID + j, hn);
        if (step >= SENC) {
            int t = step - SENC;
            d_hseq[((size_t)b * TDEC + t) * HID + j] = hn;
        }
        global_barrier();
    }
}

// ---------------- bf16 hi/lo split conversions ----------------
__global__ __launch_bounds__(256) void convW_kernel(const float* __restrict__ W)
{
    int i = blockIdx.x * 256 + threadIdx.x;           // float4 index
    const int n4 = VOC * HID / 4;
    if (i >= n4) return;
    float4 v = ((const float4*)W)[i];
    __nv_bfloat16 h0 = __float2bfloat16_rn(v.x);
    __nv_bfloat16 h1 = __float2bfloat16_rn(v.y);
    __nv_bfloat16 h2 = __float2bfloat16_rn(v.z);
    __nv_bfloat16 h3 = __float2bfloat16_rn(v.w);
    __nv_bfloat16 l0 = __float2bfloat16_rn(v.x - __bfloat162float(h0));
    __nv_bfloat16 l1 = __float2bfloat16_rn(v.y - __bfloat162float(h1));
    __nv_bfloat16 l2 = __float2bfloat16_rn(v.z - __bfloat162float(h2));
    __nv_bfloat16 l3 = __float2bfloat16_rn(v.w - __bfloat162float(h3));
    __nv_bfloat162* ph = (__nv_bfloat162*)d_Bhi;
    __nv_bfloat162* pl = (__nv_bfloat162*)d_Blo;
    ph[2 * i]     = __halves2bfloat162(h0, h1);
    ph[2 * i + 1] = __halves2bfloat162(h2, h3);
    pl[2 * i]     = __halves2bfloat162(l0, l1);
    pl[2 * i + 1] = __halves2bfloat162(l2, l3);
}

__global__ __launch_bounds__(256) void convA_kernel()
{
    int i = blockIdx.x * 256 + threadIdx.x;           // float4 index
    const int n4 = MPAD * HID / 4;
    if (i >= n4) return;
    int m = (4 * i) / HID;
    float4 v = make_float4(0.f, 0.f, 0.f, 0.f);
    if (m < MROWS) v = ((const float4*)d_hseq)[i];
    __nv_bfloat16 h0 = __float2bfloat16_rn(v.x);
    __nv_bfloat16 h1 = __float2bfloat16_rn(v.y);
    __nv_bfloat16 h2 = __float2bfloat16_rn(v.z);
    __nv_bfloat16 h3 = __float2bfloat16_rn(v.w);
    __nv_bfloat16 l0 = __float2bfloat16_rn(v.x - __bfloat162float(h0));
    __nv_bfloat16 l1 = __float2bfloat16_rn(v.y - __bfloat162float(h1));
    __nv_bfloat16 l2 = __float2bfloat16_rn(v.z - __bfloat162float(h2));
    __nv_bfloat16 l3 = __float2bfloat16_rn(v.w - __bfloat162float(h3));
    __nv_bfloat162* ph = (__nv_bfloat162*)d_Ahi;
    __nv_bfloat162* pl = (__nv_bfloat162*)d_Alo;
    ph[2 * i]     = __halves2bfloat162(h0, h1);
    ph[2 * i + 1] = __halves2bfloat162(h2, h3);
    pl[2 * i]     = __halves2bfloat162(l0, l1);
    pl[2 * i + 1] = __halves2bfloat162(l2, l3);
}

// ---------------- FC via mma.sync bf16 3-term split ----------------
// D[128x128] per CTA. 8 warps (2m x 4n), warp tile 64x32, BK=32.
// 48 K-iterations: pass 0 Ahi*Bhi, pass 1 Ahi*Blo, pass 2 Alo*Bhi, all
// accumulated into the same fp32 registers. cp.async double buffering.
// smem: row = 64B (32 bf16), chunk swizzle c ^= (row>>1)&3 -> ldmatrix
// conflict-free.
#define FC_ITERS 48

__global__ __launch_bounds__(256) void fc_mma_kernel(
    const float* __restrict__ bias, float* __restrict__ out)
{
    __shared__ uint4 As[2][512];   // 128 rows x 32 bf16, swizzled
    __shared__ uint4 Bs[2][512];

    const int tid  = threadIdx.x;
    const int wid  = tid >> 5;
    const int lane = tid & 31;
    const int m0   = blockIdx.x * 128;     // fast dim: 16 m-tiles share one B tile
    const int n0   = blockIdx.y * 128;

    const int wm = (wid >> 2) * 64;        // warp m offset within tile (0,64)
    const int wn = (wid & 3) * 32;         // warp n offset within tile (0..96)

    const uint32_t aBase = smem_u32(&As[0][0]);
    const uint32_t bBase = smem_u32(&Bs[0][0]);

    // precomputed ldmatrix addresses (per-lane constants, relative to buffer 0)
    uint32_t aAddr[4][2], bAddr[2][2];
#pragma unroll
    for (int mt = 0; mt < 4; mt++)
#pragma unroll
        for (int ks = 0; ks < 2; ks++) {
            int row = wm + mt * 16 + (lane & 15);
            int c   = ks * 2 + (lane >> 4);
            aAddr[mt][ks] = aBase + row * 64 + ((c ^ ((row >> 1) & 3)) << 4);
        }
#pragma unroll
    for (int nt2 = 0; nt2 < 2; nt2++)
#pragma unroll
        for (int ks = 0; ks < 2; ks++) {
            int row = wn + nt2 * 16 + (lane & 15);
            int c   = ks * 2 + (lane >> 4);
            bAddr[nt2][ks] = bBase + row * 64 + ((c ^ ((row >> 1) & 3)) << 4);
        }

    float acc[4][4][4];
#pragma unroll
    for (int mt = 0; mt < 4; mt++)
#pragma unroll
        for (int nt = 0; nt < 4; nt++)
#pragma unroll
            for (int r = 0; r < 4; r++) acc[mt][nt][r] = 0.0f;

    // per-thread load source (2 x 16B chunks per operand per iter)
    const int lr0 = tid >> 2;              // rows lr0, lr0+64
    const int lc  = tid & 3;               // 16B chunk within row
    const uint32_t swz0 = (uint32_t)(lr0 * 64 + ((lc ^ ((lr0 >> 1) & 3)) << 4));
    const uint32_t swz1 = (uint32_t)((lr0 + 64) * 64 + ((lc ^ (((lr0 + 64) >> 1) & 3)) << 4));

#define LOAD_TILE(it, buf) do {                                               \
    int _p  = (it) >> 4;                                                      \
    int _kb = ((it) & 15) * 32;                                               \
    const __nv_bfloat16* _gA = (_p == 2) ? d_Alo : d_Ahi;                     \
    const __nv_bfloat16* _gB = (_p == 1) ? d_Blo : d_Bhi;                     \
    const char* _sa0 = (const char*)(_gA + (size_t)(m0 + lr0) * HID + _kb + lc * 8);      \
    const char* _sa1 = (const char*)(_gA + (size_t)(m0 + lr0 + 64) * HID + _kb + lc * 8); \
    const char* _sb0 = (const char*)(_gB + (size_t)(n0 + lr0) * HID + _kb + lc * 8);      \
    const char* _sb1 = (const char*)(_gB + (size_t)(n0 + lr0 + 64) * HID + _kb + lc * 8); \
    uint32_t _ab = aBase + (buf) * 8192;                                      \
    uint32_t _bb = bBase + (buf) * 8192;                                      \
    CP_ASYNC16(_ab - aBase + aBase + (swz0), _sa0);                           \
    CP_ASYNC16(_ab + swz1 - 0, _sa1);                                         \
    CP_ASYNC16(_bb + swz0, _sb0);                                             \
    CP_ASYNC16(_bb + swz1, _sb1);                                             \
} while (0)

    LOAD_TILE(0, 0);
    CP_COMMIT();

    for (int it = 0; it < FC_ITERS; it++) {
        const int buf = it & 1;
        if (it + 1 < FC_ITERS) LOAD_TILE(it + 1, buf ^ 1);
        CP_COMMIT();
        CP_WAIT1();
        __syncthreads();

        const uint32_t boff = buf * 8192;
#pragma unroll
        for (int ks = 0; ks < 2; ks++) {
            uint32_t a[4][4];
#pragma unroll
            for (int mt = 0; mt < 4; mt++)
                ldmatrix_x4(a[mt][0], a[mt][1], a[mt][2], a[mt][3],
                            aAddr[mt][ks] + boff);
            uint32_t bb[2][4];
#pragma unroll
            for (int nt2 = 0; nt2 < 2; nt2++)
                ldmatrix_x4(bb[nt2][0], bb[nt2][1], bb[nt2][2], bb[nt2][3],
                            bAddr[nt2][ks] + boff);
#pragma unroll
            for (int mt = 0; mt < 4; mt++)
#pragma unroll
                for (int nt = 0; nt < 4; nt++) {
                    uint32_t b0 = (nt & 1) ? bb[nt >> 1][1] : bb[nt >> 1][0];
                    uint32_t b1 = (nt & 1) ? bb[nt >> 1][3] : bb[nt >> 1][2];
                    mma_16816(acc[mt][nt], a[mt], b0, b1);
                }
        }
        __syncthreads();
    }

    // ---- epilogue: add bias, write to out[b][t+1][v] ----
    const int g   = lane >> 2;            // groupID
    const int tig = lane & 3;
#pragma unroll
    for (int mt = 0; mt < 4; mt++) {
#pragma unroll
        for (int half = 0; half < 2; half++) {
            int m = m0 + wm + mt * 16 + g + half * 8;
            if (m >= MROWS) continue;
            int bidx = m / TDEC;
            int tt   = m - bidx * TDEC;
            float* orow = out + ((size_t)bidx * 32 + tt + 1) * VOC;
#pragma unroll
            for (int nt = 0; nt < 4; nt++) {
                int n = n0 + wn + nt * 8 + tig * 2;
                float b0 = __ldg(bias + n);
                float b1 = __ldg(bias + n + 1);
                float2 v = make_float2(acc[mt][nt][half * 2 + 0] + b0,
                                       acc[mt][nt][half * 2 + 1] + b1);
                *(float2*)(orow + n) = v;
            }
        }
    }
}

// ---------------- zero out[:, 0, :] ----------------
__global__ void zero_t0_kernel(float* __restrict__ out)
{
    int idx = blockIdx.x * blockDim.x + threadIdx.x;
    const int n4 = BATCH * (VOC / 4);
    if (idx < n4) {
        int b  = idx / (VOC / 4);
        int v4 = idx - b * (VOC / 4);
        ((float4*)(out + (size_t)b * 32 * VOC))[v4] = make_float4(0.f, 0.f, 0.f, 0.f);
    }
}

// ---------------- launch ----------------
extern "C" void kernel_launch(void* const* d_in, const int* in_sizes, int n_in,
                              void* d_out, int out_size)
{
    const int*   src     = (const int*)  d_in[0];
    const int*   tgt     = (const int*)  d_in[1];
    const float* enc_emb = (const float*)d_in[2];
    const float* dec_emb = (const float*)d_in[3];
    const float* enc_Wih = (const float*)d_in[4];
    const float* enc_Whh = (const float*)d_in[5];
    const float* enc_bih = (const float*)d_in[6];
    const float* enc_bhh = (const float*)d_in[7];
    const float* dec_Wih = (const float*)d_in[8];
    const float* dec_Whh = (const float*)d_in[9];
    const float* dec_bih = (const float*)d_in[10];
    const float* dec_bhh = (const float*)d_in[11];
    const float* fc_W    = (const float*)d_in[12];
    const float* fc_b    = (const float*)d_in[13];
    float* out = (float*)d_out;

    xp_gemm_kernel<<<dim3(G4 / 64, SENC), 256>>>(src, SENC, enc_emb, enc_Wih,
                                                 enc_bih, enc_bhh, 0);
    xp_gemm_kernel<<<dim3(G4 / 64, TDEC), 256>>>(tgt, 32 /* tgt row stride */,
                                                 dec_emb, dec_Wih, dec_bih, dec_bhh, 1);
    convW_kernel<<<(VOC * HID / 4 + 255) / 256, 256>>>(fc_W);
    scan_kernel<<<NBLK, 256>>>(enc_Whh, dec_Whh);
    convA_kernel<<<(MPAD * HID / 4 + 255) / 256, 256>>>();
    zero_t0_kernel<<<(BATCH * (VOC / 4) + 255) / 256, 256>>>(out);
    fc_mma_kernel<<<dim3(MPAD / 128, VOC / 128), 256>>>(fc_b, out);
}

// round 6
// speedup vs baseline: 1.5155x; 1.1279x over previous
#include <cuda_runtime.h>
#include <cuda_bf16.h>
#include <math.h>
#include <stdint.h>

#define BATCH 64
#define SENC  64
#define TDEC  31          // decoder steps = T-1
#define EMB   256
#define HID   512
#define G4    2048        // 4*H
#define VOC   32000
#define NBLK  128         // persistent scan blocks (all resident: 128 < 148 SMs)
#define MROWS (BATCH * TDEC)   // 1984 rows into FC
#define MPAD  2048             // padded FC rows (16 x 128)
#define KSTEPS (HID / 8)       // 64 k8-steps
#define NT8    (VOC / 8)       // 4000 n8 tiles

// ---------------- scratch (device globals; no allocation) ----------------
__device__ float d_xp_enc[SENC * BATCH * G4];   // [t][b][g]
__device__ float d_xp_dec[TDEC * BATCH * G4];   // [t][b][g]
__device__ float d_hbuf[2][BATCH * HID];        // ping-pong h
__device__ float d_hseq[MROWS * HID];           // [b*31+t][h] decoder outputs
__device__ unsigned d_bar_count = 0;
__device__ unsigned d_bar_gen   = 0;

// tf32 fragment-major operands for the FC GEMM
// A: [m16 tile][k8 step][lane][4 regs]   (MPAD/16 = 128 tiles)
// B: [n8 tile ][k8 step][lane][2 regs]   (4000 tiles)
__device__ float d_Af[(MPAD / 16) * KSTEPS * 32 * 4];
__device__ float d_Bf[NT8 * KSTEPS * 32 * 2];

// ---------------- helpers ----------------
__device__ __forceinline__ uint32_t smem_u32(const void* p) {
    uint32_t a;
    asm("{ .reg .u64 t; cvta.to.shared.u64 t, %1; cvt.u32.u64 %0, t; }"
        : "=r"(a) : "l"(p));
    return a;
}
#define CP_ASYNC16(dst, src) \
    asm volatile("cp.async.cg.shared.global [%0], [%1], 16;" \
                 :: "r"(dst), "l"(src) : "memory")
#define CP_COMMIT() asm volatile("cp.async.commit_group;" ::: "memory")
#define CP_WAIT1()  asm volatile("cp.async.wait_group 1;" ::: "memory")

__device__ __forceinline__ float tf32_rna(float x) {
    float r;
    asm("cvt.rna.tf32.f32 %0, %1;" : "=f"(r) : "f"(x));
    return r;
}
__device__ __forceinline__ void mma_tf32(float* c, const uint32_t* a,
                                         uint32_t b0, uint32_t b1)
{
    asm volatile("mma.sync.aligned.m16n8k8.row.col.f32.tf32.tf32.f32 "
                 "{%0,%1,%2,%3}, {%4,%5,%6,%7}, {%8,%9}, {%0,%1,%2,%3};"
                 : "+f"(c[0]), "+f"(c[1]), "+f"(c[2]), "+f"(c[3])
                 : "r"(a[0]), "r"(a[1]), "r"(a[2]), "r"(a[3]), "r"(b0), "r"(b1));
}

// ---------------- software grid barrier (all NBLK blocks resident) ----------------
__device__ __forceinline__ void global_barrier()
{
    __syncthreads();
    if (threadIdx.x == 0) {
        unsigned gen = *((volatile unsigned*)&d_bar_gen);
        __threadfence();
        unsigned arrived = atomicAdd(&d_bar_count, 1);
        if (arrived == NBLK - 1) {
            d_bar_count = 0;
            __threadfence();
            *((volatile unsigned*)&d_bar_gen) = gen + 1;
        } else {
            while (*((volatile unsigned*)&d_bar_gen) == gen) { __nanosleep(40); }
        }
        __threadfence();
    }
    __syncthreads();
}

__device__ __forceinline__ float sigm(float x) { return 1.0f / (1.0f + expf(-x)); }

// ---------------- xp = emb[tokens] @ Wih^T + bih + bhh ----------------
__global__ __launch_bounds__(256) void xp_gemm_kernel(
    const int*   __restrict__ tokens, int tok_stride,
    const float* __restrict__ emb,
    const float* __restrict__ Wih,
    const float* __restrict__ bih,
    const float* __restrict__ bhh,
    int which)
{
    __shared__ float As[16][68];
    __shared__ float Bs[16][68];

    float* __restrict__ xp = which ? d_xp_dec : d_xp_enc;

    const int tid = threadIdx.x;
    const int n0  = blockIdx.x * 64;
    const int t   = blockIdx.y;
    const int m0  = t * 64;

    const int lr  = tid >> 2;
    const int lk4 = (tid & 3) * 4;

    const int tok = tokens[lr * tok_stride + t];
    const float* arow = emb + (size_t)tok * EMB;
    const float* brow = Wih + (size_t)(n0 + lr) * EMB;

    const int tm = (tid >> 4) * 4;
    const int tn = (tid & 15) * 4;

    float acc[4][4];
#pragma unroll
    for (int i = 0; i < 4; i++)
#pragma unroll
        for (int j = 0; j < 4; j++) acc[i][j] = 0.0f;

    for (int kc = 0; kc < EMB; kc += 16) {
        float4 av = *(const float4*)(arow + kc + lk4);
        float4 bv = *(const float4*)(brow + kc + lk4);
        __syncthreads();
        As[lk4 + 0][lr] = av.x; As[lk4 + 1][lr] = av.y;
        As[lk4 + 2][lr] = av.z; As[lk4 + 3][lr] = av.w;
        Bs[lk4 + 0][lr] = bv.x; Bs[lk4 + 1][lr] = bv.y;
        Bs[lk4 + 2][lr] = bv.z; Bs[lk4 + 3][lr] = bv.w;
        __syncthreads();
#pragma unroll
        for (int k = 0; k < 16; k++) {
            float4 a = *(const float4*)&As[k][tm];
            float4 b = *(const float4*)&Bs[k][tn];
            float af[4] = {a.x, a.y, a.z, a.w};
            float bf[4] = {b.x, b.y, b.z, b.w};
#pragma unroll
            for (int i = 0; i < 4; i++)
#pragma unroll
                for (int j = 0; j < 4; j++)
                    acc[i][j] += af[i] * bf[j];
        }
    }

#pragma unroll
    for (int j = 0; j < 4; j++) {
        int n = n0 + tn + j;
        float bsum = bih[n] + bhh[n];
#pragma unroll
        for (int i = 0; i < 4; i++) {
            int m = m0 + tm + i;
            xp[(size_t)m * G4 + n] = acc[i][j] + bsum;
        }
    }
}

// ---------------- persistent LSTM scan ----------------
__global__ __launch_bounds__(256, 1) void scan_kernel(
    const float* __restrict__ encWhh,
    const float* __restrict__ decWhh)
{
    __shared__ float ws[16][516];
    __shared__ float hs[2][64][20];

    const int tid = threadIdx.x;
    const int bid = blockIdx.x;
    const int b   = tid >> 2;
    const int jj  = tid & 3;
    const int j0  = bid * 4;
    const int j   = j0 + jj;
    const int lk4 = jj * 4;

    d_hbuf[0][b * HID + j] = 0.0f;
    float c = 0.0f;

    {
        const int n    = tid >> 4;
        const int gate = n >> 2, jl = n & 3;
        const float* row = encWhh + (size_t)(gate * HID + j0 + jl) * HID;
        const int k4 = (tid & 15) * 4;
#pragma unroll
        for (int it = 0; it < 8; it++)
            *(float4*)&ws[n][k4 + it * 64] = *(const float4*)(row + k4 + it * 64);
    }
    __syncthreads();
    global_barrier();

    for (int step = 0; step < SENC + TDEC; step++) {
        if (step == SENC) {
            __syncthreads();
            const int n    = tid >> 4;
            const int gate = n >> 2, jl = n & 3;
            const float* row = decWhh + (size_t)(gate * HID + j0 + jl) * HID;
            const int k4 = (tid & 15) * 4;
#pragma unroll
            for (int it = 0; it < 8; it++)
                *(float4*)&ws[n][k4 + it * 64] = *(const float4*)(row + k4 + it * 64);
            __syncthreads();
        }

        const float* __restrict__ hprev = d_hbuf[step & 1];
        float*       __restrict__ hnext = d_hbuf[(step & 1) ^ 1];
        const float* __restrict__ xp_t  =
            (step < SENC) ? (d_xp_enc + (size_t)step * BATCH * G4)
                          : (d_xp_dec + (size_t)(step - SENC) * BATCH * G4);

        float acc0 = 0.f, acc1 = 0.f, acc2 = 0.f, acc3 = 0.f;

        float4 pv = __ldcg((const float4*)(hprev + b * HID + lk4));
        int buf = 0;
        for (int kc = 0; kc < HID; kc += 16) {
            *(float4*)&hs[buf][b][lk4] = pv;
            __syncthreads();
            if (kc + 16 < HID)
                pv = __ldcg((const float4*)(hprev + b * HID + kc + 16 + lk4));
#pragma unroll
            for (int k = 0; k < 16; k += 4) {
                float4 hv = *(const float4*)&hs[buf][b][k];
                float4 w0 = *(const float4*)&ws[0 * 4 + jj][kc + k];
                float4 w1 = *(const float4*)&ws[1 * 4 + jj][kc + k];
                float4 w2 = *(const float4*)&ws[2 * 4 + jj][kc + k];
                float4 w3 = *(const float4*)&ws[3 * 4 + jj][kc + k];
                acc0 += hv.x * w0.x; acc0 += hv.y * w0.y; acc0 += hv.z * w0.z; acc0 += hv.w * w0.w;
                acc1 += hv.x * w1.x; acc1 += hv.y * w1.y; acc1 += hv.z * w1.z; acc1 += hv.w * w1.w;
                acc2 += hv.x * w2.x; acc2 += hv.y * w2.y; acc2 += hv.z * w2.z; acc2 += hv.w * w2.w;
                acc3 += hv.x * w3.x; acc3 += hv.y * w3.y; acc3 += hv.z * w3.z; acc3 += hv.w * w3.w;
            }
            buf ^= 1;
        }

        const float* xpp = xp_t + (size_t)b * G4 + j;
        acc0 += xpp[0];
        acc1 += xpp[512];
        acc2 += xpp[1024];
        acc3 += xpp[1536];

        float ig = sigm(acc0);
        float fg = sigm(acc1);
        float gg = tanhf(acc2);
        float og = sigm(acc3);
        c = fg * c + ig * gg;
        float hn = og * tanhf(c);

        __stcg(hnext + b * HID + j, hn);
        if (step >= SENC) {
            int t = step - SENC;
            d_hseq[((size_t)b * TDEC + t) * HID + j] = hn;
        }
        global_barrier();
    }
}

// ---------------- fragment-layout conversions (fp32 -> tf32 frag-major) ----------------
// A frag (m16n8k8 row operand): thread lane (g=lane>>2, tig=lane&3) holds
//   a0=A[g][tig], a1=A[g+8][tig], a2=A[g][tig+4], a3=A[g+8][tig+4]
__global__ __launch_bounds__(256) void convA_frag_kernel()
{
    int idx = blockIdx.x * 256 + threadIdx.x;   // one float4 per (mt, ks, lane)
    const int total = (MPAD / 16) * KSTEPS * 32;
    if (idx >= total) return;
    int lane = idx & 31;
    int ks   = (idx >> 5) % KSTEPS;
    int mt   = idx / (32 * KSTEPS);
    int g    = lane >> 2, tig = lane & 3;
    int m0   = mt * 16 + g;
    int k0   = ks * 8 + tig;

    float a0 = 0.f, a1 = 0.f, a2 = 0.f, a3 = 0.f;
    if (m0 < MROWS)     { a0 = d_hseq[(size_t)m0 * HID + k0];
                          a2 = d_hseq[(size_t)m0 * HID + k0 + 4]; }
    if (m0 + 8 < MROWS) { a1 = d_hseq[(size_t)(m0 + 8) * HID + k0];
                          a3 = d_hseq[(size_t)(m0 + 8) * HID + k0 + 4]; }
    float4 v = make_float4(tf32_rna(a0), tf32_rna(a1), tf32_rna(a2), tf32_rna(a3));
    ((float4*)d_Af)[idx] = v;
}

// B frag (col operand): thread lane holds b0=B[k=tig][n=g], b1=B[k=tig+4][n=g]
// with B[k][n] = fc_W[n][k]  (W is [V, H] row-major)
__global__ __launch_bounds__(256) void convB_frag_kernel(const float* __restrict__ W)
{
    int idx = blockIdx.x * 256 + threadIdx.x;   // one float2 per (nt8, ks, lane)
    const int total = NT8 * KSTEPS * 32;
    if (idx >= total) return;
    int lane = idx & 31;
    int ks   = (idx >> 5) % KSTEPS;
    int nt   = idx / (32 * KSTEPS);
    int g    = lane >> 2, tig = lane & 3;
    int n    = nt * 8 + g;
    int k0   = ks * 8 + tig;

    float b0 = W[(size_t)n * HID + k0];
    float b1 = W[(size_t)n * HID + k0 + 4];
    ((float2*)d_Bf)[idx] = make_float2(tf32_rna(b0), tf32_rna(b1));
}

// ---------------- FC via single-pass tf32 mma.sync ----------------
// Tile 128x128, BK=32 (4 k8-steps/iter), 16 iters, double-buffered cp.async.
// smem holds fragment-major data: A [8 mt][4 ks][32 lane][4]  (16 KB)
//                                 B [16 nt8][4 ks][32 lane][2] (16 KB)
// All LDS are lane-consecutive vectors -> conflict-free, no ldmatrix.
#define FC_ITERS 16
#define ABUF 16384
#define BBUF 16384
#define FC_SMEM (2 * (ABUF + BBUF))   // 64 KB

__global__ __launch_bounds__(256, 2) void fc_mma_kernel(
    const float* __restrict__ bias, float* __restrict__ out)
{
    extern __shared__ char smem[];
    const uint32_t aBase = smem_u32(smem);              // A buffers: [0, 32KB)
    const uint32_t bBase = aBase + 2 * ABUF;            // B buffers: [32KB, 64KB)

    const int tid  = threadIdx.x;
    const int wid  = tid >> 5;
    const int lane = tid & 31;
    const int m0   = blockIdx.x * 128;     // fast dim: 16 m-tiles share one B tile
    const int n0   = blockIdx.y * 128;

    const int mtW  = (wid >> 2) * 4;       // warp's first local m16 tile (0 or 4)
    const int ntW  = (wid & 3) * 4;        // warp's first local n8 tile (0,4,8,12)

    float acc[4][4][4];
#pragma unroll
    for (int mt = 0; mt < 4; mt++)
#pragma unroll
        for (int nt = 0; nt < 4; nt++)
#pragma unroll
            for (int r = 0; r < 4; r++) acc[mt][nt][r] = 0.0f;

    // cp.async source/dest mapping
    // A: per (mtL 0..7, ks 0..3): 512B block; thread: mtL = tid>>5, copies 4 blocks' lane-slice
    const int a_mtL  = tid >> 5;
    const int a_lane = tid & 31;
    // B: per (ntL 0..15, ks 0..3): 256B block; thread: ntL = tid>>4, inner = tid&15
    const int b_ntL  = tid >> 4;
    const int b_in   = tid & 15;

#define LOAD_TILE(it, buf) do {                                                  \
    int _ks0 = (it) * 4;                                                         \
    const float* _ga = d_Af + (((size_t)(m0 / 16 + a_mtL) * KSTEPS + _ks0) * 128); \
    uint32_t _sa = aBase + (buf) * ABUF + (a_mtL * 4) * 512 + a_lane * 16;       \
    _Pragma("unroll")                                                            \
    for (int _c = 0; _c < 4; _c++)                                               \
        CP_ASYNC16(_sa + _c * 512, (const char*)(_ga + _c * 128 + a_lane * 4));  \
    const float* _gb = d_Bf + (((size_t)(n0 / 8 + b_ntL) * KSTEPS + _ks0) * 64); \
    uint32_t _sb = bBase + (buf) * BBUF + (b_ntL * 4) * 256 + b_in * 16;         \
    _Pragma("unroll")                                                            \
    for (int _c = 0; _c < 4; _c++)                                               \
        CP_ASYNC16(_sb + _c * 256, (const char*)(_gb + _c * 64 + b_in * 4));     \
} while (0)

    LOAD_TILE(0, 0);
    CP_COMMIT();

    for (int it = 0; it < FC_ITERS; it++) {
        const int buf = it & 1;
        if (it + 1 < FC_ITERS) LOAD_TILE(it + 1, buf ^ 1);
        CP_COMMIT();
        CP_WAIT1();
        __syncthreads();

        const uint32_t aOff = aBase + buf * ABUF;
        const uint32_t bOff = bBase + buf * BBUF;
#pragma unroll
        for (int ks = 0; ks < 4; ks++) {
            uint32_t a[4][4];
#pragma unroll
            for (int mt = 0; mt < 4; mt++) {
                uint32_t addr = aOff + ((mtW + mt) * 4 + ks) * 512 + lane * 16;
                asm volatile("ld.shared.v4.b32 {%0,%1,%2,%3}, [%4];"
                             : "=r"(a[mt][0]), "=r"(a[mt][1]),
                               "=r"(a[mt][2]), "=r"(a[mt][3]) : "r"(addr));
            }
            uint32_t b[4][2];
#pragma unroll
            for (int nt = 0; nt < 4; nt++) {
                uint32_t addr = bOff + ((ntW + nt) * 4 + ks) * 256 + lane * 8;
                asm volatile("ld.shared.v2.b32 {%0,%1}, [%2];"
                             : "=r"(b[nt][0]), "=r"(b[nt][1]) : "r"(addr));
            }
#pragma unroll
            for (int mt = 0; mt < 4; mt++)
#pragma unroll
                for (int nt = 0; nt < 4; nt++)
                    mma_tf32(acc[mt][nt], a[mt], b[nt][0], b[nt][1]);
        }
        __syncthreads();
    }

    // ---- epilogue: add bias, write to out[b][t+1][v] ----
    const int g   = lane >> 2;
    const int tig = lane & 3;
#pragma unroll
    for (int mt = 0; mt < 4; mt++) {
#pragma unroll
        for (int half = 0; half < 2; half++) {
            int m = m0 + (mtW + mt) * 16 + g + half * 8;
            if (m >= MROWS) continue;
            int bidx = m / TDEC;
            int tt   = m - bidx * TDEC;
            float* orow = out + ((size_t)bidx * 32 + tt + 1) * VOC;
#pragma unroll
            for (int nt = 0; nt < 4; nt++) {
                int n = n0 + (ntW + nt) * 8 + tig * 2;
                float b0 = __ldg(bias + n);
                float b1 = __ldg(bias + n + 1);
                float2 v = make_float2(acc[mt][nt][half * 2 + 0] + b0,
                                       acc[mt][nt][half * 2 + 1] + b1);
                *(float2*)(orow + n) = v;
            }
        }
    }
}

// ---------------- zero out[:, 0, :] ----------------
__global__ void zero_t0_kernel(float* __restrict__ out)
{
    int idx = blockIdx.x * blockDim.x + threadIdx.x;
    const int n4 = BATCH * (VOC / 4);
    if (idx < n4) {
        int b  = idx / (VOC / 4);
        int v4 = idx - b * (VOC / 4);
        ((float4*)(out + (size_t)b * 32 * VOC))[v4] = make_float4(0.f, 0.f, 0.f, 0.f);
    }
}

// ---------------- launch ----------------
extern "C" void kernel_launch(void* const* d_in, const int* in_sizes, int n_in,
                              void* d_out, int out_size)
{
    const int*   src     = (const int*)  d_in[0];
    const int*   tgt     = (const int*)  d_in[1];
    const float* enc_emb = (const float*)d_in[2];
    const float* dec_emb = (const float*)d_in[3];
    const float* enc_Wih = (const float*)d_in[4];
    const float* enc_Whh = (const float*)d_in[5];
    const float* enc_bih = (const float*)d_in[6];
    const float* enc_bhh = (const float*)d_in[7];
    const float* dec_Wih = (const float*)d_in[8];
    const float* dec_Whh = (const float*)d_in[9];
    const float* dec_bih = (const float*)d_in[10];
    const float* dec_bhh = (const float*)d_in[11];
    const float* fc_W    = (const float*)d_in[12];
    const float* fc_b    = (const float*)d_in[13];
    float* out = (float*)d_out;

    static int smem_set = 0;
    if (!smem_set) {
        cudaFuncSetAttribute(fc_mma_kernel,
                             cudaFuncAttributeMaxDynamicSharedMemorySize, FC_SMEM);
        smem_set = 1;
    }

    xp_gemm_kernel<<<dim3(G4 / 64, SENC), 256>>>(src, SENC, enc_emb, enc_Wih,
                                                 enc_bih, enc_bhh, 0);
    xp_gemm_kernel<<<dim3(G4 / 64, TDEC), 256>>>(tgt, 32 /* tgt row stride */,
                                                 dec_emb, dec_Wih, dec_bih, dec_bhh, 1);
    convB_frag_kernel<<<(NT8 * KSTEPS * 32 + 255) / 256, 256>>>(fc_W);
    scan_kernel<<<NBLK, 256>>>(enc_Whh, dec_Whh);
    convA_frag_kernel<<<((MPAD / 16) * KSTEPS * 32 + 255) / 256, 256>>>();
    zero_t0_kernel<<<(BATCH * (VOC / 4) + 255) / 256, 256>>>(out);
    fc_mma_kernel<<<dim3(MPAD / 128, VOC / 128), 256, FC_SMEM>>>(fc_b, out);
}

// round 7
// speedup vs baseline: 1.7903x; 1.1813x over previous
#include <cuda_runtime.h>
#include <cuda_bf16.h>
#include <math.h>
#include <stdint.h>

#define BATCH 64
#define SENC  64
#define TDEC  31          // decoder steps = T-1
#define EMB   256
#define HID   512
#define G4    2048        // 4*H
#define VOC   32000
#define NBLK  128         // persistent scan blocks (all resident, 1 block/SM)
#define MROWS (BATCH * TDEC)   // 1984 rows into FC
#define MPAD  2048             // padded FC rows (16 x 128)
#define KSTEPS (HID / 8)       // 64 k8-steps
#define NT8    (VOC / 8)       // 4000 n8 tiles

// ---------------- scratch (device globals; no allocation) ----------------
__device__ float d_xp_enc[SENC * BATCH * G4];   // [t][b][g]
__device__ float d_xp_dec[TDEC * BATCH * G4];   // [t][b][g]
__device__ float d_hbuf[2][BATCH * HID];        // ping-pong h
__device__ float d_hseq[MROWS * HID];           // [b*31+t][h] decoder outputs
__device__ unsigned d_bar_count = 0;
__device__ unsigned d_bar_gen   = 0;

// tf32 fragment-major operands for the FC GEMM
__device__ float d_Af[(MPAD / 16) * KSTEPS * 32 * 4];
__device__ float d_Bf[NT8 * KSTEPS * 32 * 2];

// Whh fragment-major, gate-permuted: [layer][bid][nt(2)][ks(64)][lane(32)][2]
__device__ float d_WhhF[2 * NBLK * 2 * KSTEPS * 32 * 2];

// ---------------- helpers ----------------
__device__ __forceinline__ uint32_t smem_u32(const void* p) {
    uint32_t a;
    asm("{ .reg .u64 t; cvta.to.shared.u64 t, %1; cvt.u32.u64 %0, t; }"
        : "=r"(a) : "l"(p));
    return a;
}
#define CP_ASYNC16(dst, src) \
    asm volatile("cp.async.cg.shared.global [%0], [%1], 16;" \
                 :: "r"(dst), "l"(src) : "memory")
#define CP_COMMIT() asm volatile("cp.async.commit_group;" ::: "memory")
#define CP_WAIT1()  asm volatile("cp.async.wait_group 1;" ::: "memory")

__device__ __forceinline__ float tf32_rna(float x) {
    float r;
    asm("cvt.rna.tf32.f32 %0, %1;" : "=f"(r) : "f"(x));
    return r;
}
__device__ __forceinline__ void mma_tf32(float* c, const uint32_t* a,
                                         uint32_t b0, uint32_t b1)
{
    asm volatile("mma.sync.aligned.m16n8k8.row.col.f32.tf32.tf32.f32 "
                 "{%0,%1,%2,%3}, {%4,%5,%6,%7}, {%8,%9}, {%0,%1,%2,%3};"
                 : "+f"(c[0]), "+f"(c[1]), "+f"(c[2]), "+f"(c[3])
                 : "r"(a[0]), "r"(a[1]), "r"(a[2]), "r"(a[3]), "r"(b0), "r"(b1));
}

// ---------------- software grid barrier (all NBLK blocks resident) ----------------
__device__ __forceinline__ void global_barrier()
{
    __syncthreads();
    if (threadIdx.x == 0) {
        unsigned gen = *((volatile unsigned*)&d_bar_gen);
        __threadfence();
        unsigned arrived = atomicAdd(&d_bar_count, 1);
        if (arrived == NBLK - 1) {
            d_bar_count = 0;
            __threadfence();
            *((volatile unsigned*)&d_bar_gen) = gen + 1;
        } else {
            while (*((volatile unsigned*)&d_bar_gen) == gen) { __nanosleep(40); }
        }
        __threadfence();
    }
    __syncthreads();
}

__device__ __forceinline__ float sigm(float x) { return 1.0f / (1.0f + expf(-x)); }

// ---------------- xp = emb[tokens] @ Wih^T + bih + bhh ----------------
__global__ __launch_bounds__(256) void xp_gemm_kernel(
    const int*   __restrict__ tokens, int tok_stride,
    const float* __restrict__ emb,
    const float* __restrict__ Wih,
    const float* __restrict__ bih,
    const float* __restrict__ bhh,
    int which)
{
    __shared__ float As[16][68];
    __shared__ float Bs[16][68];

    float* __restrict__ xp = which ? d_xp_dec : d_xp_enc;

    const int tid = threadIdx.x;
    const int n0  = blockIdx.x * 64;
    const int t   = blockIdx.y;
    const int m0  = t * 64;

    const int lr  = tid >> 2;
    const int lk4 = (tid & 3) * 4;

    const int tok = tokens[lr * tok_stride + t];
    const float* arow = emb + (size_t)tok * EMB;
    const float* brow = Wih + (size_t)(n0 + lr) * EMB;

    const int tm = (tid >> 4) * 4;
    const int tn = (tid & 15) * 4;

    float acc[4][4];
#pragma unroll
    for (int i = 0; i < 4; i++)
#pragma unroll
        for (int j = 0; j < 4; j++) acc[i][j] = 0.0f;

    for (int kc = 0; kc < EMB; kc += 16) {
        float4 av = *(const float4*)(arow + kc + lk4);
        float4 bv = *(const float4*)(brow + kc + lk4);
        __syncthreads();
        As[lk4 + 0][lr] = av.x; As[lk4 + 1][lr] = av.y;
        As[lk4 + 2][lr] = av.z; As[lk4 + 3][lr] = av.w;
        Bs[lk4 + 0][lr] = bv.x; Bs[lk4 + 1][lr] = bv.y;
        Bs[lk4 + 2][lr] = bv.z; Bs[lk4 + 3][lr] = bv.w;
        __syncthreads();
#pragma unroll
        for (int k = 0; k < 16; k++) {
            float4 a = *(const float4*)&As[k][tm];
            float4 b = *(const float4*)&Bs[k][tn];
            float af[4] = {a.x, a.y, a.z, a.w};
            float bf[4] = {b.x, b.y, b.z, b.w};
#pragma unroll
            for (int i = 0; i < 4; i++)
#pragma unroll
                for (int j = 0; j < 4; j++)
                    acc[i][j] += af[i] * bf[j];
        }
    }

#pragma unroll
    for (int j = 0; j < 4; j++) {
        int n = n0 + tn + j;
        float bsum = bih[n] + bhh[n];
#pragma unroll
        for (int i = 0; i < 4; i++) {
            int m = m0 + tm + i;
            xp[(size_t)m * G4 + n] = acc[i][j] + bsum;
        }
    }
}

// ---------------- Whh -> gate-permuted tf32 fragments ----------------
// For scan block bid, local col nn (0..15): j = bid*4 + nn/4, gate = nn%4.
// Fragment lane (g=lane>>2, tig=lane&3): b0 = Whh[gate*512+j][ks*8+tig],
// b1 = same row, k+4.  Layout: [layer][bid][nt][ks][lane][2]
__global__ __launch_bounds__(256) void convWhh_frag_kernel(
    const float* __restrict__ encWhh, const float* __restrict__ decWhh)
{
    int idx = blockIdx.x * 256 + threadIdx.x;
    if (idx >= 2 * NBLK * 2 * KSTEPS * 32) return;
    int lane  = idx & 31;
    int ks    = (idx >> 5) & 63;
    int nt    = (idx >> 11) & 1;
    int bid   = (idx >> 12) & 127;
    int layer = idx >> 19;

    int g = lane >> 2, tig = lane & 3;
    int nn   = nt * 8 + g;
    int j    = bid * 4 + (nn >> 2);
    int gate = nn & 3;
    const float* W = layer ? decWhh : encWhh;
    const float* row = W + (size_t)(gate * HID + j) * HID + ks * 8 + tig;
    ((float2*)d_WhhF)[idx] = make_float2(tf32_rna(row[0]), tf32_rna(row[4]));
}

// ---------------- persistent LSTM scan on tensor cores ----------------
// 128 blocks; block owns 4 hidden cols (all 4 gates via permuted Whh frags).
// 8 warps = 4 m16-tiles x 2 n8-tiles. c-state in registers (1 per lane).
#define HPITCH 516
#define SCAN_SMEM ((64 * HPITCH + 2 * KSTEPS * 32 * 2) * 4)   // 164864 B

__global__ __launch_bounds__(256, 1) void scan_tc_kernel()
{
    extern __shared__ float sm[];
    float* h_s = sm;                      // [64][HPITCH]
    float* wf  = sm + 64 * HPITCH;        // [2][64][32][2] frags

    const int tid  = threadIdx.x;
    const int bid  = blockIdx.x;
    const int wid  = tid >> 5;
    const int lane = tid & 31;
    const int mt   = wid & 3;
    const int nt   = wid >> 2;
    const int g    = lane >> 2;
    const int tig  = lane & 3;
    const int odd  = lane & 1;

    const int row0 = mt * 16 + g;                 // A-frag row
    const int myb  = mt * 16 + g + odd * 8;       // pointwise (batch, col)
    const int myj  = bid * 4 + nt * 2 + (tig >> 1);

    // h0 = 0 (each block zeroes its own 4 cols x 64 batches)
    d_hbuf[0][(tid >> 2) * HID + bid * 4 + (tid & 3)] = 0.0f;
    float c = 0.0f;

    // load encoder Whh frags (8192 floats)
    {
        const float4* src = (const float4*)(d_WhhF + (size_t)bid * 8192);
#pragma unroll
        for (int i = 0; i < 8; i++)
            ((float4*)wf)[tid + i * 256] = src[tid + i * 256];
    }
    __syncthreads();
    global_barrier();                    // h0 visible everywhere

    for (int step = 0; step < SENC + TDEC; step++) {
        if (step == SENC) {              // swap to decoder Whh frags
            __syncthreads();
            const float4* src = (const float4*)(d_WhhF + (size_t)(NBLK + bid) * 8192);
#pragma unroll
            for (int i = 0; i < 8; i++)
                ((float4*)wf)[tid + i * 256] = src[tid + i * 256];
            __syncthreads();
        }

        const float* __restrict__ hprev = d_hbuf[step & 1];
        float*       __restrict__ hnext = d_hbuf[(step & 1) ^ 1];
        const float* __restrict__ xp_t  =
            (step < SENC) ? (d_xp_enc + (size_t)step * BATCH * G4)
                          : (d_xp_dec + (size_t)(step - SENC) * BATCH * G4);

        // stage h (tf32-rounded values) into padded smem, coalesced
#pragma unroll
        for (int i = 0; i < 32; i++) {
            int q = tid + i * 256;               // 8192 float4s
            int r = q >> 7, c4 = (q & 127) * 4;
            float4 v = __ldcg((const float4*)(hprev + r * HID + c4));
            *(float4*)&h_s[r * HPITCH + c4] = v;
        }
        __syncthreads();

        float acc[4] = {0.f, 0.f, 0.f, 0.f};
        const float* ap = &h_s[row0 * HPITCH + tig];
        const float* bp = &wf[(nt * KSTEPS) * 64 + lane * 2];
#pragma unroll 8
        for (int ks = 0; ks < KSTEPS; ks++) {
            uint32_t a[4];
            a[0] = __float_as_uint(ap[ks * 8]);
            a[2] = __float_as_uint(ap[ks * 8 + 4]);
            a[1] = __float_as_uint(ap[ks * 8 + 8 * HPITCH]);
            a[3] = __float_as_uint(ap[ks * 8 + 8 * HPITCH + 4]);
            float2 b = *(const float2*)(bp + ks * 64);
            mma_tf32(acc, a, __float_as_uint(b.x), __float_as_uint(b.y));
        }

        // reassemble gates: even lane has (i,f) rows g/g+8; odd has (g,o)
        float o0 = __shfl_xor_sync(0xFFFFFFFFu, acc[0], 1);
        float o1 = __shfl_xor_sync(0xFFFFFFFFu, acc[1], 1);
        float o2 = __shfl_xor_sync(0xFFFFFFFFu, acc[2], 1);
        float o3 = __shfl_xor_sync(0xFFFFFFFFu, acc[3], 1);
        float pi, pf, pg, po;
        if (!odd) { pi = acc[0]; pf = acc[1]; pg = o0;     po = o1;     }
        else      { pi = o2;     pf = o3;     pg = acc[2]; po = acc[3]; }

        const float* xb = xp_t + (size_t)myb * G4 + myj;
        pi += __ldcg(xb);
        pf += __ldcg(xb + 512);
        pg += __ldcg(xb + 1024);
        po += __ldcg(xb + 1536);

        c = sigm(pf) * c + sigm(pi) * tanhf(pg);
        float hn = sigm(po) * tanhf(c);
        float hr = tf32_rna(hn);

        __stcg(&hnext[myb * HID + myj], hr);
        if (step >= SENC) {
            int t = step - SENC;
            d_hseq[((size_t)myb * TDEC + t) * HID + myj] = hr;
        }
        global_barrier();
    }
}

// ---------------- fragment-layout conversions (fp32 -> tf32 frag-major) ----------------
__global__ __launch_bounds__(256) void convA_frag_kernel()
{
    int idx = blockIdx.x * 256 + threadIdx.x;   // one float4 per (mt, ks, lane)
    const int total = (MPAD / 16) * KSTEPS * 32;
    if (idx >= total) return;
    int lane = idx & 31;
    int ks   = (idx >> 5) % KSTEPS;
    int mt   = idx / (32 * KSTEPS);
    int g    = lane >> 2, tig = lane & 3;
    int m0   = mt * 16 + g;
    int k0   = ks * 8 + tig;

    float a0 = 0.f, a1 = 0.f, a2 = 0.f, a3 = 0.f;
    if (m0 < MROWS)     { a0 = d_hseq[(size_t)m0 * HID + k0];
                          a2 = d_hseq[(size_t)m0 * HID + k0 + 4]; }
    if (m0 + 8 < MROWS) { a1 = d_hseq[(size_t)(m0 + 8) * HID + k0];
                          a3 = d_hseq[(size_t)(m0 + 8) * HID + k0 + 4]; }
    float4 v = make_float4(tf32_rna(a0), tf32_rna(a1), tf32_rna(a2), tf32_rna(a3));
    ((float4*)d_Af)[idx] = v;
}

__global__ __launch_bounds__(256) void convB_frag_kernel(const float* __restrict__ W)
{
    int idx = blockIdx.x * 256 + threadIdx.x;   // one float2 per (nt8, ks, lane)
    const int total = NT8 * KSTEPS * 32;
    if (idx >= total) return;
    int lane = idx & 31;
    int ks   = (idx >> 5) % KSTEPS;
    int nt   = idx / (32 * KSTEPS);
    int g    = lane >> 2, tig = lane & 3;
    int n    = nt * 8 + g;
    int k0   = ks * 8 + tig;

    float b0 = W[(size_t)n * HID + k0];
    float b1 = W[(size_t)n * HID + k0 + 4];
    ((float2*)d_Bf)[idx] = make_float2(tf32_rna(b0), tf32_rna(b1));
}

// ---------------- FC via single-pass tf32 mma.sync ----------------
#define FC_ITERS 16
#define ABUF 16384
#define BBUF 16384
#define FC_SMEM (2 * (ABUF + BBUF))   // 64 KB

__global__ __launch_bounds__(256, 2) void fc_mma_kernel(
    const float* __restrict__ bias, float* __restrict__ out)
{
    extern __shared__ char smem[];
    const uint32_t aBase = smem_u32(smem);
    const uint32_t bBase = aBase + 2 * ABUF;

    const int tid  = threadIdx.x;
    const int wid  = tid >> 5;
    const int lane = tid & 31;
    const int m0   = blockIdx.x * 128;
    const int n0   = blockIdx.y * 128;

    const int mtW  = (wid >> 2) * 4;
    const int ntW  = (wid & 3) * 4;

    float acc[4][4][4];
#pragma unroll
    for (int mt = 0; mt < 4; mt++)
#pragma unroll
        for (int nt = 0; nt < 4; nt++)
#pragma unroll
            for (int r = 0; r < 4; r++) acc[mt][nt][r] = 0.0f;

    const int a_mtL  = tid >> 5;
    const int a_lane = tid & 31;
    const int b_ntL  = tid >> 4;
    const int b_in   = tid & 15;

#define LOAD_TILE(it, buf) do {                                                  \
    int _ks0 = (it) * 4;                                                         \
    const float* _ga = d_Af + (((size_t)(m0 / 16 + a_mtL) * KSTEPS + _ks0) * 128); \
    uint32_t _sa = aBase + (buf) * ABUF + (a_mtL * 4) * 512 + a_lane * 16;       \
    _Pragma("unroll")                                                            \
    for (int _c = 0; _c < 4; _c++)                                               \
        CP_ASYNC16(_sa + _c * 512, (const char*)(_ga + _c * 128 + a_lane * 4));  \
    const float* _gb = d_Bf + (((size_t)(n0 / 8 + b_ntL) * KSTEPS + _ks0) * 64); \
    uint32_t _sb = bBase + (buf) * BBUF + (b_ntL * 4) * 256 + b_in * 16;         \
    _Pragma("unroll")                                                            \
    for (int _c = 0; _c < 4; _c++)                                               \
        CP_ASYNC16(_sb + _c * 256, (const char*)(_gb + _c * 64 + b_in * 4));     \
} while (0)

    LOAD_TILE(0, 0);
    CP_COMMIT();

    for (int it = 0; it < FC_ITERS; it++) {
        const int buf = it & 1;
        if (it + 1 < FC_ITERS) LOAD_TILE(it + 1, buf ^ 1);
        CP_COMMIT();
        CP_WAIT1();
        __syncthreads();

        const uint32_t aOff = aBase + buf * ABUF;
        const uint32_t bOff = bBase + buf * BBUF;
#pragma unroll
        for (int ks = 0; ks < 4; ks++) {
            uint32_t a[4][4];
#pragma unroll
            for (int mt = 0; mt < 4; mt++) {
                uint32_t addr = aOff + ((mtW + mt) * 4 + ks) * 512 + lane * 16;
                asm volatile("ld.shared.v4.b32 {%0,%1,%2,%3}, [%4];"
                             : "=r"(a[mt][0]), "=r"(a[mt][1]),
                               "=r"(a[mt][2]), "=r"(a[mt][3]) : "r"(addr));
            }
            uint32_t b[4][2];
#pragma unroll
            for (int nt = 0; nt < 4; nt++) {
                uint32_t addr = bOff + ((ntW + nt) * 4 + ks) * 256 + lane * 8;
                asm volatile("ld.shared.v2.b32 {%0,%1}, [%2];"
                             : "=r"(b[nt][0]), "=r"(b[nt][1]) : "r"(addr));
            }
#pragma unroll
            for (int mt = 0; mt < 4; mt++)
#pragma unroll
                for (int nt = 0; nt < 4; nt++)
                    mma_tf32(acc[mt][nt], a[mt], b[nt][0], b[nt][1]);
        }
        __syncthreads();
    }

    const int g   = lane >> 2;
    const int tig = lane & 3;
#pragma unroll
    for (int mt = 0; mt < 4; mt++) {
#pragma unroll
        for (int half = 0; half < 2; half++) {
            int m = m0 + (mtW + mt) * 16 + g + half * 8;
            if (m >= MROWS) continue;
            int bidx = m / TDEC;
            int tt   = m - bidx * TDEC;
            float* orow = out + ((size_t)bidx * 32 + tt + 1) * VOC;
#pragma unroll
            for (int nt = 0; nt < 4; nt++) {
                int n = n0 + (ntW + nt) * 8 + tig * 2;
                float b0 = __ldg(bias + n);
                float b1 = __ldg(bias + n + 1);
                float2 v = make_float2(acc[mt][nt][half * 2 + 0] + b0,
                                       acc[mt][nt][half * 2 + 1] + b1);
                *(float2*)(orow + n) = v;
            }
        }
    }
}

// ---------------- zero out[:, 0, :] ----------------
__global__ void zero_t0_kernel(float* __restrict__ out)
{
    int idx = blockIdx.x * blockDim.x + threadIdx.x;
    const int n4 = BATCH * (VOC / 4);
    if (idx < n4) {
        int b  = idx / (VOC / 4);
        int v4 = idx - b * (VOC / 4);
        ((float4*)(out + (size_t)b * 32 * VOC))[v4] = make_float4(0.f, 0.f, 0.f, 0.f);
    }
}

// ---------------- launch ----------------
extern "C" void kernel_launch(void* const* d_in, const int* in_sizes, int n_in,
                              void* d_out, int out_size)
{
    const int*   src     = (const int*)  d_in[0];
    const int*   tgt     = (const int*)  d_in[1];
    const float* enc_emb = (const float*)d_in[2];
    const float* dec_emb = (const float*)d_in[3];
    const float* enc_Wih = (const float*)d_in[4];
    const float* enc_Whh = (const float*)d_in[5];
    const float* enc_bih = (const float*)d_in[6];
    const float* enc_bhh = (const float*)d_in[7];
    const float* dec_Wih = (const float*)d_in[8];
    const float* dec_Whh = (const float*)d_in[9];
    const float* dec_bih = (const float*)d_in[10];
    const float* dec_bhh = (const float*)d_in[11];
    const float* fc_W    = (const float*)d_in[12];
    const float* fc_b    = (const float*)d_in[13];
    float* out = (float*)d_out;

    static int attr_set = 0;
    if (!attr_set) {
        cudaFuncSetAttribute(fc_mma_kernel,
                             cudaFuncAttributeMaxDynamicSharedMemorySize, FC_SMEM);
        cudaFuncSetAttribute(scan_tc_kernel,
                             cudaFuncAttributeMaxDynamicSharedMemorySize, SCAN_SMEM);
        attr_set = 1;
    }

    xp_gemm_kernel<<<dim3(G4 / 64, SENC), 256>>>(src, SENC, enc_emb, enc_Wih,
                                                 enc_bih, enc_bhh, 0);
    xp_gemm_kernel<<<dim3(G4 / 64, TDEC), 256>>>(tgt, 32 /* tgt row stride */,
                                                 dec_emb, dec_Wih, dec_bih, dec_bhh, 1);
    convWhh_frag_kernel<<<(2 * NBLK * 2 * KSTEPS * 32 + 255) / 256, 256>>>(enc_Whh, dec_Whh);
    convB_frag_kernel<<<(NT8 * KSTEPS * 32 + 255) / 256, 256>>>(fc_W);
    scan_tc_kernel<<<NBLK, 256, SCAN_SMEM>>>();
    convA_frag_kernel<<<((MPAD / 16) * KSTEPS * 32 + 255) / 256, 256>>>();
    zero_t0_kernel<<<(BATCH * (VOC / 4) + 255) / 256, 256>>>(out);
    fc_mma_kernel<<<dim3(MPAD / 128, VOC / 128), 256, FC_SMEM>>>(fc_b, out);
}

// round 8
// speedup vs baseline: 2.7576x; 1.5403x over previous
#include <cuda_runtime.h>
#include <cuda_bf16.h>
#include <math.h>
#include <stdint.h>

#define BATCH 64
#define SENC  64
#define TDEC  31          // decoder steps = T-1
#define EMB   256
#define HID   512
#define G4    2048        // 4*H
#define VOC   32000
#define SNBLK 64          // persistent scan blocks (all resident)
#define MROWS (BATCH * TDEC)   // 1984 rows into FC
#define MPAD  2048             // padded FC rows (16 x 128)
#define KSTEPS (HID / 8)       // 64 k8-steps (FC / scan K)
#define EKSTEPS (EMB / 8)      // 32 k8-steps (xp K)
#define NT8    (VOC / 8)       // 4000 n8 tiles

// ---------------- scratch (device globals; no allocation) ----------------
__device__ float d_xp_enc[SENC * BATCH * G4];   // [t][b][g]
__device__ float d_xp_dec[TDEC * BATCH * G4];   // [t][b][g]
__device__ float d_hbuf[2][BATCH * HID];        // ping-pong h
__device__ float d_hseq[MROWS * HID];           // [b*31+t][h] decoder outputs
__device__ unsigned d_bar_count = 0;
__device__ unsigned d_bar_gen   = 0;

// tf32 fragment-major operands
__device__ float d_Af[(MPAD / 16) * KSTEPS * 32 * 4];
__device__ float d_Bf[NT8 * KSTEPS * 32 * 2];
// Wih frags: [layer][n8(256)][ks(32)][lane(32)][2]
__device__ float d_WihF[2 * 256 * EKSTEPS * 32 * 2];
// Whh frags gate-permuted: [layer][bid(64)][nt(4)][ks(64)][lane(32)][2]
__device__ float d_WhhF[2 * SNBLK * 4 * KSTEPS * 32 * 2];

// ---------------- helpers ----------------
__device__ __forceinline__ uint32_t smem_u32(const void* p) {
    uint32_t a;
    asm("{ .reg .u64 t; cvta.to.shared.u64 t, %1; cvt.u32.u64 %0, t; }"
        : "=r"(a) : "l"(p));
    return a;
}
#define CP_ASYNC16(dst, src) \
    asm volatile("cp.async.cg.shared.global [%0], [%1], 16;" \
                 :: "r"(dst), "l"(src) : "memory")
#define CP_COMMIT() asm volatile("cp.async.commit_group;" ::: "memory")
#define CP_WAIT1()  asm volatile("cp.async.wait_group 1;" ::: "memory")
#define CP_WAITN(n) asm volatile("cp.async.wait_group %0;" :: "n"(n) : "memory")

__device__ __forceinline__ float tf32_rna(float x) {
    float r;
    asm("cvt.rna.tf32.f32 %0, %1;" : "=f"(r) : "f"(x));
    return r;
}
__device__ __forceinline__ void mma_tf32(float* c, const uint32_t* a,
                                         uint32_t b0, uint32_t b1)
{
    asm volatile("mma.sync.aligned.m16n8k8.row.col.f32.tf32.tf32.f32 "
                 "{%0,%1,%2,%3}, {%4,%5,%6,%7}, {%8,%9}, {%0,%1,%2,%3};"
                 : "+f"(c[0]), "+f"(c[1]), "+f"(c[2]), "+f"(c[3])
                 : "r"(a[0]), "r"(a[1]), "r"(a[2]), "r"(a[3]), "r"(b0), "r"(b1));
}

// ---------------- software grid barrier (SNBLK resident blocks) ----------------
__device__ __forceinline__ void global_barrier()
{
    __syncthreads();
    if (threadIdx.x == 0) {
        unsigned gen = *((volatile unsigned*)&d_bar_gen);
        __threadfence();
        unsigned arrived = atomicAdd(&d_bar_count, 1);
        if (arrived == SNBLK - 1) {
            d_bar_count = 0;
            __threadfence();
            *((volatile unsigned*)&d_bar_gen) = gen + 1;
        } else {
            while (*((volatile unsigned*)&d_bar_gen) == gen) { __nanosleep(20); }
        }
        __threadfence();
    }
    __syncthreads();
}

__device__ __forceinline__ float sigm(float x) { return 1.0f / (1.0f + expf(-x)); }

// ---------------- Wih -> tf32 fragments ----------------
__global__ __launch_bounds__(256) void convWih_frag_kernel(
    const float* __restrict__ encWih, const float* __restrict__ decWih)
{
    int idx = blockIdx.x * 256 + threadIdx.x;     // one float2
    if (idx >= 2 * 256 * EKSTEPS * 32) return;
    int lane  = idx & 31;
    int ks    = (idx >> 5) & 31;
    int nt    = (idx >> 10) & 255;
    int layer = idx >> 18;
    int g = lane >> 2, tig = lane & 3;
    const float* W = layer ? decWih : encWih;
    const float* row = W + (size_t)(nt * 8 + g) * EMB + ks * 8 + tig;
    ((float2*)d_WihF)[idx] = make_float2(tf32_rna(row[0]), tf32_rna(row[4]));
}

// ---------------- xp via tf32 mma: xp[t][b][n] = emb[tok[b,t]] . Wih[n] + bias ----------------
// grid (16 n-tiles, 95 t). CTA: 64 rows (batches) x 128 cols. A gathered to smem.
#define XP_PITCH 260
#define XP_SMEM (64 * XP_PITCH * 4)   // 66560 B

__global__ __launch_bounds__(256, 2) void xp_mma_kernel(
    const int*   __restrict__ src,  const int* __restrict__ tgt,
    const float* __restrict__ enc_emb, const float* __restrict__ dec_emb,
    const float* __restrict__ enc_bih, const float* __restrict__ enc_bhh,
    const float* __restrict__ dec_bih, const float* __restrict__ dec_bhh)
{
    extern __shared__ float a_s[];

    const int tid  = threadIdx.x;
    const int wid  = tid >> 5;
    const int lane = tid & 31;
    const int n0   = blockIdx.x * 128;
    const int t    = blockIdx.y;

    const int*   toks; const float* emb; const float* bi; const float* bh;
    const float* WF; float* xp; int tloc, tstride;
    if (t < SENC) {
        toks = src; emb = enc_emb; bi = enc_bih; bh = enc_bhh;
        WF = d_WihF; xp = d_xp_enc + (size_t)t * BATCH * G4;
        tloc = t; tstride = SENC;
    } else {
        toks = tgt; emb = dec_emb; bi = dec_bih; bh = dec_bhh;
        WF = d_WihF + 256 * EKSTEPS * 32 * 2;
        xp = d_xp_dec + (size_t)(t - SENC) * BATCH * G4;
        tloc = t - SENC; tstride = 32;
    }

    // gather 64 emb rows (256 floats each) into padded smem
#pragma unroll
    for (int i = 0; i < 16; i++) {
        int q  = tid + i * 256;           // 4096 float4s
        int r  = q >> 6;
        int c4 = (q & 63) * 4;
        int tok = __ldg(toks + r * tstride + tloc);
        float4 v = __ldg((const float4*)(emb + (size_t)tok * EMB + c4));
        *(float4*)&a_s[r * XP_PITCH + c4] = v;
    }
    __syncthreads();

    const int mt = wid >> 1;              // m16 tile 0..3
    const int nh = wid & 1;               // n half (8 n8-tiles each)
    const int g  = lane >> 2, tig = lane & 3;

    float acc[8][4];
#pragma unroll
    for (int nt = 0; nt < 8; nt++)
#pragma unroll
        for (int r = 0; r < 4; r++) acc[nt][r] = 0.0f;

    const int n8base = n0 / 8 + nh * 8;
    const float* ap = &a_s[(mt * 16 + g) * XP_PITCH + tig];

    for (int ks = 0; ks < EKSTEPS; ks++) {
        uint32_t a[4];
        a[0] = __float_as_uint(tf32_rna(ap[ks * 8]));
        a[2] = __float_as_uint(tf32_rna(ap[ks * 8 + 4]));
        a[1] = __float_as_uint(tf32_rna(ap[ks * 8 + 8 * XP_PITCH]));
        a[3] = __float_as_uint(tf32_rna(ap[ks * 8 + 8 * XP_PITCH + 4]));
#pragma unroll
        for (int nt = 0; nt < 8; nt++) {
            float2 b = __ldg((const float2*)(WF +
                       (((size_t)(n8base + nt) * EKSTEPS + ks) * 32 + lane) * 2));
            mma_tf32(acc[nt], a, __float_as_uint(b.x), __float_as_uint(b.y));
        }
    }

    // epilogue
#pragma unroll
    for (int nt = 0; nt < 8; nt++) {
        int n = (n8base + nt) * 8 + tig * 2;
        float b0 = __ldg(bi + n) + __ldg(bh + n);
        float b1 = __ldg(bi + n + 1) + __ldg(bh + n + 1);
        int r0 = mt * 16 + g;
        *(float2*)(xp + (size_t)r0 * G4 + n) =
            make_float2(acc[nt][0] + b0, acc[nt][1] + b1);
        *(float2*)(xp + (size_t)(r0 + 8) * G4 + n) =
            make_float2(acc[nt][2] + b0, acc[nt][3] + b1);
    }
}

// ---------------- Whh -> gate-permuted tf32 fragments ----------------
// block bid owns 8 j cols -> 32 N-cols; tile nt covers nn = nt*8+g;
// j = bid*8 + nn/4, gate = nn%4.
__global__ __launch_bounds__(256) void convWhh_frag_kernel(
    const float* __restrict__ encWhh, const float* __restrict__ decWhh)
{
    int idx = blockIdx.x * 256 + threadIdx.x;     // one float2
    if (idx >= 2 * SNBLK * 4 * KSTEPS * 32) return;
    int lane  = idx & 31;
    int ks    = (idx >> 5) & 63;
    int nt    = (idx >> 11) & 3;
    int bid   = (idx >> 13) & 63;
    int layer = idx >> 19;

    int g = lane >> 2, tig = lane & 3;
    int nn   = nt * 8 + g;
    int j    = bid * 8 + (nn >> 2);
    int gate = nn & 3;
    const float* W = layer ? decWhh : encWhh;
    const float* row = W + (size_t)(gate * HID + j) * HID + ks * 8 + tig;
    ((float2*)d_WhhF)[idx] = make_float2(tf32_rna(row[0]), tf32_rna(row[4]));
}

// ---------------- persistent LSTM scan on tensor cores, 64 blocks ----------------
// block owns 8 j (4 n8 tiles, gate-permuted). 8 warps = 4 mt x 2 nt-pairs.
// h staged via cp.async in 4 pipelined chunks of 128 cols.
#define HCH   132
#define WFLT  (4 * KSTEPS * 32 * 2)                 // 16384 floats of Whh frags
#define SCAN_SMEM ((WFLT + 4 * 64 * HCH) * 4)       // 200704 B

__global__ __launch_bounds__(256, 1) void scan_tc_kernel()
{
    extern __shared__ float sm[];
    float* wf  = sm;                    // [4 nt][64 ks][32 lane][2]
    float* h_s = sm + WFLT;             // [4 chunk][64 b][HCH]
    const uint32_t hBase = smem_u32(h_s);

    const int tid  = threadIdx.x;
    const int bid  = blockIdx.x;
    const int wid  = tid >> 5;
    const int lane = tid & 31;
    const int mt   = wid & 3;
    const int ntp  = (wid >> 2) * 2;     // first of 2 n8 tiles
    const int g    = lane >> 2;
    const int tig  = lane & 3;
    const int odd  = lane & 1;

    const int row0 = mt * 16 + g;
    const int myb  = mt * 16 + g + odd * 8;
    const int j0   = bid * 8 + ntp * 2 + (tig >> 1);
    const int j1   = j0 + 2;

    // h0 = 0 (this block's 8 cols x 64 batches)
#pragma unroll
    for (int i = 0; i < 2; i++) {
        int e = tid + i * 256;
        d_hbuf[0][(e >> 3) * HID + bid * 8 + (e & 7)] = 0.0f;
    }
    float c0 = 0.0f, c1 = 0.0f;

    // load encoder Whh frags (16384 floats)
    {
        const float4* s = (const float4*)(d_WhhF + (size_t)bid * WFLT);
#pragma unroll
        for (int i = 0; i < 16; i++)
            ((float4*)wf)[tid + i * 256] = s[tid + i * 256];
    }
    __syncthreads();
    global_barrier();

    for (int step = 0; step < SENC + TDEC; step++) {
        if (step == SENC) {
            __syncthreads();
            const float4* s = (const float4*)(d_WhhF + (size_t)(SNBLK + bid) * WFLT);
#pragma unroll
            for (int i = 0; i < 16; i++)
                ((float4*)wf)[tid + i * 256] = s[tid + i * 256];
            __syncthreads();
        }

        const float* __restrict__ hprev = d_hbuf[step & 1];
        float*       __restrict__ hnext = d_hbuf[(step & 1) ^ 1];
        const float* __restrict__ xp_t  =
            (step < SENC) ? (d_xp_enc + (size_t)step * BATCH * G4)
                          : (d_xp_dec + (size_t)(step - SENC) * BATCH * G4);

        // prefetch xp gate values (independent of h)
        const float* xb0 = xp_t + (size_t)myb * G4 + j0;
        const float* xb1 = xp_t + (size_t)myb * G4 + j1;
        float xi0 = __ldcg(xb0),        xf0 = __ldcg(xb0 + 512);
        float xg0 = __ldcg(xb0 + 1024), xo0 = __ldcg(xb0 + 1536);
        float xi1 = __ldcg(xb1),        xf1 = __ldcg(xb1 + 512);
        float xg1 = __ldcg(xb1 + 1024), xo1 = __ldcg(xb1 + 1536);

        // stage h in 4 chunks of 128 cols via cp.async (pipelined)
#pragma unroll
        for (int ch = 0; ch < 4; ch++) {
#pragma unroll
            for (int i = 0; i < 8; i++) {
                int q  = tid + i * 256;          // 2048 float4s per chunk
                int r  = q >> 5;
                int c4 = (q & 31) * 4;
                CP_ASYNC16(hBase + (ch * 64 * HCH + r * HCH + c4) * 4,
                           hprev + (size_t)r * HID + ch * 128 + c4);
            }
            CP_COMMIT();
        }

        float acc[2][4];
#pragma unroll
        for (int u = 0; u < 2; u++)
#pragma unroll
            for (int r = 0; r < 4; r++) acc[u][r] = 0.0f;

#pragma unroll
        for (int ch = 0; ch < 4; ch++) {
            if (ch == 0) CP_WAITN(3);
            else if (ch == 1) CP_WAITN(2);
            else if (ch == 2) CP_WAITN(1);
            else CP_WAITN(0);
            __syncthreads();

            const float* ap = &h_s[ch * 64 * HCH + row0 * HCH + tig];
            const float* bp0 = &wf[((ntp * KSTEPS + ch * 16) * 32 + lane) * 2];
            const float* bp1 = &wf[(((ntp + 1) * KSTEPS + ch * 16) * 32 + lane) * 2];
#pragma unroll
            for (int k2 = 0; k2 < 16; k2++) {
                uint32_t a[4];
                a[0] = __float_as_uint(ap[k2 * 8]);
                a[2] = __float_as_uint(ap[k2 * 8 + 4]);
                a[1] = __float_as_uint(ap[k2 * 8 + 8 * HCH]);
                a[3] = __float_as_uint(ap[k2 * 8 + 8 * HCH + 4]);
                float2 b0 = *(const float2*)(bp0 + k2 * 64);
                float2 b1 = *(const float2*)(bp1 + k2 * 64);
                mma_tf32(acc[0], a, __float_as_uint(b0.x), __float_as_uint(b0.y));
                mma_tf32(acc[1], a, __float_as_uint(b1.x), __float_as_uint(b1.y));
            }
        }

        // gate reassembly + pointwise for both tiles
#pragma unroll
        for (int u = 0; u < 2; u++) {
            float* a = acc[u];
            float o0 = __shfl_xor_sync(0xFFFFFFFFu, a[0], 1);
            float o1 = __shfl_xor_sync(0xFFFFFFFFu, a[1], 1);
            float o2 = __shfl_xor_sync(0xFFFFFFFFu, a[2], 1);
            float o3 = __shfl_xor_sync(0xFFFFFFFFu, a[3], 1);
            float pi, pf, pg, po;
            if (!odd) { pi = a[0]; pf = a[1]; pg = o0;   po = o1;   }
            else      { pi = o2;   pf = o3;   pg = a[2]; po = a[3]; }

            if (u == 0) { pi += xi0; pf += xf0; pg += xg0; po += xo0; }
            else        { pi += xi1; pf += xf1; pg += xg1; po += xo1; }

            float& cc = (u == 0) ? c0 : c1;
            cc = sigm(pf) * cc + sigm(pi) * tanhf(pg);
            float hn = sigm(po) * tanhf(cc);
            float hr = tf32_rna(hn);

            int j = (u == 0) ? j0 : j1;
            __stcg(&hnext[(size_t)myb * HID + j], hr);
            if (step >= SENC) {
                int t = step - SENC;
                d_hseq[((size_t)myb * TDEC + t) * HID + j] = hr;
            }
        }
        global_barrier();
    }
}

// ---------------- fragment-layout conversions for the FC ----------------
__global__ __launch_bounds__(256) void convA_frag_kernel()
{
    int idx = blockIdx.x * 256 + threadIdx.x;
    const int total = (MPAD / 16) * KSTEPS * 32;
    if (idx >= total) return;
    int lane = idx & 31;
    int ks   = (idx >> 5) % KSTEPS;
    int mt   = idx / (32 * KSTEPS);
    int g    = lane >> 2, tig = lane & 3;
    int m0   = mt * 16 + g;
    int k0   = ks * 8 + tig;

    float a0 = 0.f, a1 = 0.f, a2 = 0.f, a3 = 0.f;
    if (m0 < MROWS)     { a0 = d_hseq[(size_t)m0 * HID + k0];
                          a2 = d_hseq[(size_t)m0 * HID + k0 + 4]; }
    if (m0 + 8 < MROWS) { a1 = d_hseq[(size_t)(m0 + 8) * HID + k0];
                          a3 = d_hseq[(size_t)(m0 + 8) * HID + k0 + 4]; }
    float4 v = make_float4(tf32_rna(a0), tf32_rna(a1), tf32_rna(a2), tf32_rna(a3));
    ((float4*)d_Af)[idx] = v;
}

__global__ __launch_bounds__(256) void convB_frag_kernel(const float* __restrict__ W)
{
    int idx = blockIdx.x * 256 + threadIdx.x;
    const int total = NT8 * KSTEPS * 32;
    if (idx >= total) return;
    int lane = idx & 31;
    int ks   = (idx >> 5) % KSTEPS;
    int nt   = idx / (32 * KSTEPS);
    int g    = lane >> 2, tig = lane & 3;
    int n    = nt * 8 + g;
    int k0   = ks * 8 + tig;

    float b0 = W[(size_t)n * HID + k0];
    float b1 = W[(size_t)n * HID + k0 + 4];
    ((float2*)d_Bf)[idx] = make_float2(tf32_rna(b0), tf32_rna(b1));
}

// ---------------- FC via single-pass tf32 mma.sync ----------------
#define FC_ITERS 16
#define ABUF 16384
#define BBUF 16384
#define FC_SMEM (2 * (ABUF + BBUF))   // 64 KB

__global__ __launch_bounds__(256, 2) void fc_mma_kernel(
    const float* __restrict__ bias, float* __restrict__ out)
{
    extern __shared__ char smem[];
    const uint32_t aBase = smem_u32(smem);
    const uint32_t bBase = aBase + 2 * ABUF;

    const int tid  = threadIdx.x;
    const int wid  = tid >> 5;
    const int lane = tid & 31;
    const int m0   = blockIdx.x * 128;
    const int n0   = blockIdx.y * 128;

    const int mtW  = (wid >> 2) * 4;
    const int ntW  = (wid & 3) * 4;

    float acc[4][4][4];
#pragma unroll
    for (int mt = 0; mt < 4; mt++)
#pragma unroll
        for (int nt = 0; nt < 4; nt++)
#pragma unroll
            for (int r = 0; r < 4; r++) acc[mt][nt][r] = 0.0f;

    const int a_mtL  = tid >> 5;
    const int a_lane = tid & 31;
    const int b_ntL  = tid >> 4;
    const int b_in   = tid & 15;

#define LOAD_TILE(it, buf) do {                                                  \
    int _ks0 = (it) * 4;                                                         \
    const float* _ga = d_Af + (((size_t)(m0 / 16 + a_mtL) * KSTEPS + _ks0) * 128); \
    uint32_t _sa = aBase + (buf) * ABUF + (a_mtL * 4) * 512 + a_lane * 16;       \
    _Pragma("unroll")                                                            \
    for (int _c = 0; _c < 4; _c++)                                               \
        CP_ASYNC16(_sa + _c * 512, (const char*)(_ga + _c * 128 + a_lane * 4));  \
    const float* _gb = d_Bf + (((size_t)(n0 / 8 + b_ntL) * KSTEPS + _ks0) * 64); \
    uint32_t _sb = bBase + (buf) * BBUF + (b_ntL * 4) * 256 + b_in * 16;         \
    _Pragma("unroll")                                                            \
    for (int _c = 0; _c < 4; _c++)                                               \
        CP_ASYNC16(_sb + _c * 256, (const char*)(_gb + _c * 64 + b_in * 4));     \
} while (0)

    LOAD_TILE(0, 0);
    CP_COMMIT();

    for (int it = 0; it < FC_ITERS; it++) {
        const int buf = it & 1;
        if (it + 1 < FC_ITERS) LOAD_TILE(it + 1, buf ^ 1);
        CP_COMMIT();
        CP_WAIT1();
        __syncthreads();

        const uint32_t aOff = aBase + buf * ABUF;
        const uint32_t bOff = bBase + buf * BBUF;
#pragma unroll
        for (int ks = 0; ks < 4; ks++) {
            uint32_t a[4][4];
#pragma unroll
            for (int mt = 0; mt < 4; mt++) {
                uint32_t addr = aOff + ((mtW + mt) * 4 + ks) * 512 + lane * 16;
                asm volatile("ld.shared.v4.b32 {%0,%1,%2,%3}, [%4];"
                             : "=r"(a[mt][0]), "=r"(a[mt][1]),
                               "=r"(a[mt][2]), "=r"(a[mt][3]) : "r"(addr));
            }
            uint32_t b[4][2];
#pragma unroll
            for (int nt = 0; nt < 4; nt++) {
                uint32_t addr = bOff + ((ntW + nt) * 4 + ks) * 256 + lane * 8;
                asm volatile("ld.shared.v2.b32 {%0,%1}, [%2];"
                             : "=r"(b[nt][0]), "=r"(b[nt][1]) : "r"(addr));
            }
#pragma unroll
            for (int mt = 0; mt < 4; mt++)
#pragma unroll
                for (int nt = 0; nt < 4; nt++)
                    mma_tf32(acc[mt][nt], a[mt], b[nt][0], b[nt][1]);
        }
        __syncthreads();
    }

    const int g   = lane >> 2;
    const int tig = lane & 3;
#pragma unroll
    for (int mt = 0; mt < 4; mt++) {
#pragma unroll
        for (int half = 0; half < 2; half++) {
            int m = m0 + (mtW + mt) * 16 + g + half * 8;
            if (m >= MROWS) continue;
            int bidx = m / TDEC;
            int tt   = m - bidx * TDEC;
            float* orow = out + ((size_t)bidx * 32 + tt + 1) * VOC;
#pragma unroll
            for (int nt = 0; nt < 4; nt++) {
                int n = n0 + (ntW + nt) * 8 + tig * 2;
                float b0 = __ldg(bias + n);
                float b1 = __ldg(bias + n + 1);
                float2 v = make_float2(acc[mt][nt][half * 2 + 0] + b0,
                                       acc[mt][nt][half * 2 + 1] + b1);
                *(float2*)(orow + n) = v;
            }
        }
    }
}

// ---------------- zero out[:, 0, :] ----------------
__global__ void zero_t0_kernel(float* __restrict__ out)
{
    int idx = blockIdx.x * blockDim.x + threadIdx.x;
    const int n4 = BATCH * (VOC / 4);
    if (idx < n4) {
        int b  = idx / (VOC / 4);
        int v4 = idx - b * (VOC / 4);
        ((float4*)(out + (size_t)b * 32 * VOC))[v4] = make_float4(0.f, 0.f, 0.f, 0.f);
    }
}

// ---------------- launch ----------------
extern "C" void kernel_launch(void* const* d_in, const int* in_sizes, int n_in,
                              void* d_out, int out_size)
{
    const int*   src     = (const int*)  d_in[0];
    const int*   tgt     = (const int*)  d_in[1];
    const float* enc_emb = (const float*)d_in[2];
    const float* dec_emb = (const float*)d_in[3];
    const float* enc_Wih = (const float*)d_in[4];
    const float* enc_Whh = (const float*)d_in[5];
    const float* enc_bih = (const float*)d_in[6];
    const float* enc_bhh = (const float*)d_in[7];
    const float* dec_Wih = (const float*)d_in[8];
    const float* dec_Whh = (const float*)d_in[9];
    const float* dec_bih = (const float*)d_in[10];
    const float* dec_bhh = (const float*)d_in[11];
    const float* fc_W    = (const float*)d_in[12];
    const float* fc_b    = (const float*)d_in[13];
    float* out = (float*)d_out;

    static int attr_set = 0;
    if (!attr_set) {
        cudaFuncSetAttribute(fc_mma_kernel,
                             cudaFuncAttributeMaxDynamicSharedMemorySize, FC_SMEM);
        cudaFuncSetAttribute(scan_tc_kernel,
                             cudaFuncAttributeMaxDynamicSharedMemorySize, SCAN_SMEM);
        cudaFuncSetAttribute(xp_mma_kernel,
                             cudaFuncAttributeMaxDynamicSharedMemorySize, XP_SMEM);
        attr_set = 1;
    }

    convWih_frag_kernel<<<(2 * 256 * EKSTEPS * 32 + 255) / 256, 256>>>(enc_Wih, dec_Wih);
    xp_mma_kernel<<<dim3(16, SENC + TDEC), 256, XP_SMEM>>>(
        src, tgt, enc_emb, dec_emb, enc_bih, enc_bhh, dec_bih, dec_bhh);
    convWhh_frag_kernel<<<(2 * SNBLK * 4 * KSTEPS * 32 + 255) / 256, 256>>>(enc_Whh, dec_Whh);
    convB_frag_kernel<<<(NT8 * KSTEPS * 32 + 255) / 256, 256>>>(fc_W);
    scan_tc_kernel<<<SNBLK, 256, SCAN_SMEM>>>();
    convA_frag_kernel<<<((MPAD / 16) * KSTEPS * 32 + 255) / 256, 256>>>();
    zero_t0_kernel<<<(BATCH * (VOC / 4) + 255) / 256, 256>>>(out);
    fc_mma_kernel<<<dim3(MPAD / 128, VOC / 128), 256, FC_SMEM>>>(fc_b, out);
}

// round 10
// speedup vs baseline: 2.7651x; 1.0027x over previous
#include <cuda_runtime.h>
#include <cuda_fp16.h>
#include <math.h>
#include <stdint.h>

#define BATCH 64
#define SENC  64
#define TDEC  31          // decoder steps = T-1
#define EMB   256
#define HID   512
#define G4    2048        // 4*H
#define VOC   32000
#define SNBLK 64          // persistent scan blocks (all resident)
#define MROWS (BATCH * TDEC)   // 1984 rows into FC
#define MPAD  2048             // padded FC rows (16 x 128)
#define KS16  (HID / 16)       // 32 k16-steps (FC / scan K)
#define EKS16 (EMB / 16)       // 16 k16-steps (xp K)
#define NT8   (VOC / 8)        // 4000 n8 tiles

// ---------------- scratch (device globals; no allocation) ----------------
__device__ float  d_xp_enc[SENC * BATCH * G4];   // [t][b][g] fp32
__device__ float  d_xp_dec[TDEC * BATCH * G4];
__device__ __half d_hbuf[2][BATCH * HID];        // ping-pong h (fp16)
__device__ __half d_hseq[MROWS * HID];           // decoder outputs (fp16)
__device__ unsigned d_bar_count = 0;
__device__ unsigned d_bar_gen   = 0;

// fp16 fragment-major operands (packed half2 in uint32)
__device__ uint32_t d_Af[(MPAD / 16) * KS16 * 32 * 4];   // A: [mt][ks][lane][4]
__device__ uint32_t d_Bf[NT8 * KS16 * 32 * 2];           // B: [nt8][ks][lane][2]
__device__ uint32_t d_WihF[2 * 256 * EKS16 * 32 * 2];    // [layer][n8][ks][lane][2]
__device__ uint32_t d_WhhF[2 * SNBLK * 4 * KS16 * 32 * 2]; // [layer][bid][nt][ks][lane][2]

// ---------------- helpers ----------------
__device__ __forceinline__ uint32_t smem_u32(const void* p) {
    uint32_t a;
    asm("{ .reg .u64 t; cvta.to.shared.u64 t, %1; cvt.u32.u64 %0, t; }"
        : "=r"(a) : "l"(p));
    return a;
}
#define CP_ASYNC16(dst, src) \
    asm volatile("cp.async.cg.shared.global [%0], [%1], 16;" \
                 :: "r"(dst), "l"(src) : "memory")
#define CP_COMMIT() asm volatile("cp.async.commit_group;" ::: "memory")
#define CP_WAIT1()  asm volatile("cp.async.wait_group 1;" ::: "memory")
#define CP_WAITN(n) asm volatile("cp.async.wait_group %0;" :: "n"(n) : "memory")

__device__ __forceinline__ uint32_t packh2(float x, float y) {
    __half2 h = __floats2half2_rn(x, y);
    return *(uint32_t*)&h;
}
__device__ __forceinline__ void mma_f16(float* c, const uint32_t* a,
                                        uint32_t b0, uint32_t b1)
{
    asm volatile("mma.sync.aligned.m16n8k16.row.col.f32.f16.f16.f32 "
                 "{%0,%1,%2,%3}, {%4,%5,%6,%7}, {%8,%9}, {%0,%1,%2,%3};"
                 : "+f"(c[0]), "+f"(c[1]), "+f"(c[2]), "+f"(c[3])
                 : "r"(a[0]), "r"(a[1]), "r"(a[2]), "r"(a[3]), "r"(b0), "r"(b1));
}

// ---------------- software grid barrier (SNBLK resident blocks) ----------------
__device__ __forceinline__ void global_barrier()
{
    __syncthreads();
    if (threadIdx.x == 0) {
        unsigned gen = *((volatile unsigned*)&d_bar_gen);
        __threadfence();
        unsigned arrived = atomicAdd(&d_bar_count, 1);
        if (arrived == SNBLK - 1) {
            d_bar_count = 0;
            __threadfence();
            *((volatile unsigned*)&d_bar_gen) = gen + 1;
        } else {
            while (*((volatile unsigned*)&d_bar_gen) == gen) { __nanosleep(20); }
        }
        __threadfence();
    }
    __syncthreads();
}

__device__ __forceinline__ float sigm(float x) { return 1.0f / (1.0f + expf(-x)); }

// ---------------- Wih -> fp16 fragments ----------------
__global__ __launch_bounds__(256) void convWih_frag_kernel(
    const float* __restrict__ encWih, const float* __restrict__ decWih)
{
    int idx = blockIdx.x * 256 + threadIdx.x;     // one uint2
    if (idx >= 2 * 256 * EKS16 * 32) return;
    int lane  = idx & 31;
    int ks    = (idx >> 5) & (EKS16 - 1);
    int nt    = (idx >> 9) & 255;
    int layer = idx >> 17;
    int g = lane >> 2, tig = lane & 3;
    const float* W = layer ? decWih : encWih;
    const float* row = W + (size_t)(nt * 8 + g) * EMB + ks * 16 + tig * 2;
    ((uint2*)d_WihF)[idx] = make_uint2(packh2(row[0], row[1]),
                                      packh2(row[8], row[9]));
}

// ---------------- xp via fp16 mma ----------------
#define XPP 264                     // smem pitch in halves (132 words ≡ 4 mod 32)
#define XP_SMEM (64 * XPP * 2)      // 33792 B

__global__ __launch_bounds__(256, 2) void xp_mma_kernel(
    const int*   __restrict__ src,  const int* __restrict__ tgt,
    const float* __restrict__ enc_emb, const float* __restrict__ dec_emb,
    const float* __restrict__ enc_bih, const float* __restrict__ enc_bhh,
    const float* __restrict__ dec_bih, const float* __restrict__ dec_bhh)
{
    extern __shared__ __half a_s[];

    const int tid  = threadIdx.x;
    const int wid  = tid >> 5;
    const int lane = tid & 31;
    const int n0   = blockIdx.x * 128;
    const int t    = blockIdx.y;

    const int*   toks; const float* emb; const float* bi; const float* bh;
    const uint32_t* WF; float* xp; int tloc, tstride;
    if (t < SENC) {
        toks = src; emb = enc_emb; bi = enc_bih; bh = enc_bhh;
        WF = d_WihF; xp = d_xp_enc + (size_t)t * BATCH * G4;
        tloc = t; tstride = SENC;
    } else {
        toks = tgt; emb = dec_emb; bi = dec_bih; bh = dec_bhh;
        WF = d_WihF + 256 * EKS16 * 32 * 2;
        xp = d_xp_dec + (size_t)(t - SENC) * BATCH * G4;
        tloc = t - SENC; tstride = 32;
    }

    // gather 64 emb rows -> fp16 smem (8192 half2)
#pragma unroll
    for (int i = 0; i < 32; i++) {
        int q  = tid + i * 256;
        int r  = q >> 7;
        int c2 = q & 127;
        int tok = __ldg(toks + r * tstride + tloc);
        float2 v = __ldg((const float2*)(emb + (size_t)tok * EMB + c2 * 2));
        *(uint32_t*)&a_s[r * XPP + c2 * 2] = packh2(v.x, v.y);
    }
    __syncthreads();

    const int mt = wid >> 1;
    const int nh = wid & 1;
    const int g  = lane >> 2, tig = lane & 3;

    float acc[8][4];
#pragma unroll
    for (int nt = 0; nt < 8; nt++)
#pragma unroll
        for (int r = 0; r < 4; r++) acc[nt][r] = 0.0f;

    const int n8base = n0 / 8 + nh * 8;
    const __half* ap = &a_s[(mt * 16 + g) * XPP + tig * 2];

    for (int ks = 0; ks < EKS16; ks++) {
        uint32_t a[4];
        a[0] = *(const uint32_t*)(ap + ks * 16);
        a[2] = *(const uint32_t*)(ap + ks * 16 + 8);
        a[1] = *(const uint32_t*)(ap + ks * 16 + 8 * XPP);
        a[3] = *(const uint32_t*)(ap + ks * 16 + 8 * XPP + 8);
#pragma unroll
        for (int nt = 0; nt < 8; nt++) {
            uint2 b = __ldg((const uint2*)(WF +
                      (((size_t)(n8base + nt) * EKS16 + ks) * 32 + lane) * 2));
            mma_f16(acc[nt], a, b.x, b.y);
        }
    }

#pragma unroll
    for (int nt = 0; nt < 8; nt++) {
        int n = (n8base + nt) * 8 + tig * 2;
        float b0 = __ldg(bi + n) + __ldg(bh + n);
        float b1 = __ldg(bi + n + 1) + __ldg(bh + n + 1);
        int r0 = mt * 16 + g;
        *(float2*)(xp + (size_t)r0 * G4 + n) =
            make_float2(acc[nt][0] + b0, acc[nt][1] + b1);
        *(float2*)(xp + (size_t)(r0 + 8) * G4 + n) =
            make_float2(acc[nt][2] + b0, acc[nt][3] + b1);
    }
}

// ---------------- Whh -> gate-permuted fp16 fragments ----------------
__global__ __launch_bounds__(256) void convWhh_frag_kernel(
    const float* __restrict__ encWhh, const float* __restrict__ decWhh)
{
    int idx = blockIdx.x * 256 + threadIdx.x;     // one uint2
    if (idx >= 2 * SNBLK * 4 * KS16 * 32) return;
    int lane  = idx & 31;
    int ks    = (idx >> 5) & (KS16 - 1);
    int nt    = (idx >> 10) & 3;
    int bid   = (idx >> 12) & 63;
    int layer = idx >> 18;

    int g = lane >> 2, tig = lane & 3;
    int nn   = nt * 8 + g;
    int j    = bid * 8 + (nn >> 2);
    int gate = nn & 3;
    const float* W = layer ? decWhh : encWhh;
    const float* row = W + (size_t)(gate * HID + j) * HID + ks * 16 + tig * 2;
    ((uint2*)d_WhhF)[idx] = make_uint2(packh2(row[0], row[1]),
                                      packh2(row[8], row[9]));
}

// ---------------- persistent LSTM scan, fp16 tensor cores, 64 blocks ----------------
#define HPB   1040                                   // h row pitch bytes (260 words ≡ 4 mod 32)
#define WFU   (4 * KS16 * 32 * 2)                    // 8192 u32 = 32 KB
#define SCAN_SMEM (WFU * 4 + 64 * HPB)               // 99328 B

__global__ __launch_bounds__(256, 1) void scan_tc_kernel()
{
    extern __shared__ char scm[];
    uint32_t* wf = (uint32_t*)scm;                   // Whh frags
    char*     hs = scm + WFU * 4;                    // [64 rows][HPB]
    const uint32_t hBase = smem_u32(hs);

    const int tid  = threadIdx.x;
    const int bid  = blockIdx.x;
    const int wid  = tid >> 5;
    const int lane = tid & 31;
    const int mt   = wid & 3;
    const int ntp  = (wid >> 2) * 2;
    const int g    = lane >> 2;
    const int tig  = lane & 3;
    const int odd  = lane & 1;

    const int row0 = mt * 16 + g;
    const int myb  = mt * 16 + g + odd * 8;
    const int j0   = bid * 8 + ntp * 2 + (tig >> 1);
    const int j1   = j0 + 2;

    // h0 = 0
#pragma unroll
    for (int i = 0; i < 2; i++) {
        int e = tid + i * 256;
        d_hbuf[0][(e >> 3) * HID + bid * 8 + (e & 7)] = __float2half(0.0f);
    }
    float c0 = 0.0f, c1 = 0.0f;

    {   // encoder Whh frags: 8192 u32 = 2048 uint4
        const uint4* s = (const uint4*)(d_WhhF + (size_t)bid * WFU);
#pragma unroll
        for (int i = 0; i < 8; i++)
            ((uint4*)wf)[tid + i * 256] = s[tid + i * 256];
    }
    __syncthreads();
    global_barrier();

    for (int step = 0; step < SENC + TDEC; step++) {
        if (step == SENC) {
            __syncthreads();
            const uint4* s = (const uint4*)(d_WhhF + (size_t)(SNBLK + bid) * WFU);
#pragma unroll
            for (int i = 0; i < 8; i++)
                ((uint4*)wf)[tid + i * 256] = s[tid + i * 256];
            __syncthreads();
        }

        const __half* __restrict__ hprev = d_hbuf[step & 1];
        __half*       __restrict__ hnext = d_hbuf[(step & 1) ^ 1];
        const float*  __restrict__ xp_t  =
            (step < SENC) ? (d_xp_enc + (size_t)step * BATCH * G4)
                          : (d_xp_dec + (size_t)(step - SENC) * BATCH * G4);

        // prefetch xp gate values
        const float* xb0 = xp_t + (size_t)myb * G4 + j0;
        const float* xb1 = xp_t + (size_t)myb * G4 + j1;
        float xi0 = __ldcg(xb0),        xf0 = __ldcg(xb0 + 512);
        float xg0 = __ldcg(xb0 + 1024), xo0 = __ldcg(xb0 + 1536);
        float xi1 = __ldcg(xb1),        xf1 = __ldcg(xb1 + 512);
        float xg1 = __ldcg(xb1 + 1024), xo1 = __ldcg(xb1 + 1536);

        // stage h (fp16) in 4 chunks of 128 cols (256 B/row) via cp.async
#pragma unroll
        for (int ch = 0; ch < 4; ch++) {
#pragma unroll
            for (int i = 0; i < 4; i++) {
                int q  = tid + i * 256;              // 1024 16B-chunks per col-chunk
                int r  = q >> 4;
                int cb = (q & 15) * 16;
                CP_ASYNC16(hBase + r * HPB + ch * 256 + cb,
                           (const char*)hprev + (size_t)r * 1024 + ch * 256 + cb);
            }
            CP_COMMIT();
        }

        float acc[2][4];
#pragma unroll
        for (int u = 0; u < 2; u++)
#pragma unroll
            for (int r = 0; r < 4; r++) acc[u][r] = 0.0f;

#pragma unroll
        for (int ch = 0; ch < 4; ch++) {
            if (ch == 0) CP_WAITN(3);
            else if (ch == 1) CP_WAITN(2);
            else if (ch == 2) CP_WAITN(1);
            else CP_WAITN(0);
            __syncthreads();

            const char* ap = hs + row0 * HPB + ch * 256 + tig * 4;
            const uint32_t* bp0 = wf + ((ntp * KS16 + ch * 8) * 32 + lane) * 2;
            const uint32_t* bp1 = wf + (((ntp + 1) * KS16 + ch * 8) * 32 + lane) * 2;
#pragma unroll
            for (int k2 = 0; k2 < 8; k2++) {        // 8 k16-steps per chunk
                uint32_t a[4];
                a[0] = *(const uint32_t*)(ap + k2 * 32);
                a[2] = *(const uint32_t*)(ap + k2 * 32 + 16);
                a[1] = *(const uint32_t*)(ap + k2 * 32 + 8 * HPB);
                a[3] = *(const uint32_t*)(ap + k2 * 32 + 8 * HPB + 16);
                uint2 b0 = *(const uint2*)(bp0 + k2 * 64);
                uint2 b1 = *(const uint2*)(bp1 + k2 * 64);
                mma_f16(acc[0], a, b0.x, b0.y);
                mma_f16(acc[1], a, b1.x, b1.y);
            }
        }

        // gate reassembly + pointwise
#pragma unroll
        for (int u = 0; u < 2; u++) {
            float* a = acc[u];
            float o0 = __shfl_xor_sync(0xFFFFFFFFu, a[0], 1);
            float o1 = __shfl_xor_sync(0xFFFFFFFFu, a[1], 1);
            float o2 = __shfl_xor_sync(0xFFFFFFFFu, a[2], 1);
            float o3 = __shfl_xor_sync(0xFFFFFFFFu, a[3], 1);
            float pi, pf, pg, po;
            if (!odd) { pi = a[0]; pf = a[1]; pg = o0;   po = o1;   }
            else      { pi = o2;   pf = o3;   pg = a[2]; po = a[3]; }

            if (u == 0) { pi += xi0; pf += xf0; pg += xg0; po += xo0; }
            else        { pi += xi1; pf += xf1; pg += xg1; po += xo1; }

            float& cc = (u == 0) ? c0 : c1;
            cc = sigm(pf) * cc + sigm(pi) * tanhf(pg);
            __half hr = __float2half_rn(sigm(po) * tanhf(cc));

            int j = (u == 0) ? j0 : j1;
            __stcg((short*)&hnext[(size_t)myb * HID + j], *(short*)&hr);
            if (step >= SENC) {
                int t = step - SENC;
                d_hseq[((size_t)myb * TDEC + t) * HID + j] = hr;
            }
        }
        global_barrier();
    }
}

// ---------------- fragment gathers for the FC ----------------
__global__ __launch_bounds__(256) void convA_frag_kernel()
{
    int idx = blockIdx.x * 256 + threadIdx.x;        // one uint4
    const int total = (MPAD / 16) * KS16 * 32;
    if (idx >= total) return;
    int lane = idx & 31;
    int ks   = (idx >> 5) & (KS16 - 1);
    int mt   = idx / (32 * KS16);
    int g    = lane >> 2, tig = lane & 3;
    int m0   = mt * 16 + g;
    int k0   = ks * 16 + tig * 2;

    uint32_t a0 = 0, a1 = 0, a2 = 0, a3 = 0;
    if (m0 < MROWS) {
        a0 = *(const uint32_t*)&d_hseq[(size_t)m0 * HID + k0];
        a2 = *(const uint32_t*)&d_hseq[(size_t)m0 * HID + k0 + 8];
    }
    if (m0 + 8 < MROWS) {
        a1 = *(const uint32_t*)&d_hseq[(size_t)(m0 + 8) * HID + k0];
        a3 = *(const uint32_t*)&d_hseq[(size_t)(m0 + 8) * HID + k0 + 8];
    }
    ((uint4*)d_Af)[idx] = make_uint4(a0, a1, a2, a3);
}

__global__ __launch_bounds__(256) void convB_frag_kernel(const float* __restrict__ W)
{
    int idx = blockIdx.x * 256 + threadIdx.x;        // one uint2
    const int total = NT8 * KS16 * 32;
    if (idx >= total) return;
    int lane = idx & 31;
    int ks   = (idx >> 5) & (KS16 - 1);
    int nt   = idx / (32 * KS16);
    int g    = lane >> 2, tig = lane & 3;
    const float* row = W + (size_t)(nt * 8 + g) * HID + ks * 16 + tig * 2;
    ((uint2*)d_Bf)[idx] = make_uint2(packh2(row[0], row[1]),
                                    packh2(row[8], row[9]));
}

// ---------------- FC via fp16 mma.sync ----------------
#define FC_ITERS 8
#define ABUF 16384
#define BBUF 16384
#define FC_SMEM (2 * (ABUF + BBUF))   // 64 KB

__global__ __launch_bounds__(256, 2) void fc_mma_kernel(
    const float* __restrict__ bias, float* __restrict__ out)
{
    extern __shared__ char smem[];
    const uint32_t aBase = smem_u32(smem);
    const uint32_t bBase = aBase + 2 * ABUF;

    const int tid  = threadIdx.x;
    const int wid  = tid >> 5;
    const int lane = tid & 31;
    const int m0   = blockIdx.x * 128;     // fast dim: m-tiles share B via L2
    const int n0   = blockIdx.y * 128;

    const int mtW  = (wid >> 2) * 4;
    const int ntW  = (wid & 3) * 4;

    float acc[4][4][4];
#pragma unroll
    for (int mt = 0; mt < 4; mt++)
#pragma unroll
        for (int nt = 0; nt < 4; nt++)
#pragma unroll
            for (int r = 0; r < 4; r++) acc[mt][nt][r] = 0.0f;

    const int a_mtL  = tid >> 5;
    const int a_lane = tid & 31;
    const int b_ntL  = tid >> 4;
    const int b_in   = tid & 15;

#define LOAD_TILE(it, buf) do {                                                  \
    int _ks0 = (it) * 4;                                                         \
    const uint32_t* _ga = d_Af + (((size_t)(m0 / 16 + a_mtL) * KS16 + _ks0) * 128); \
    uint32_t _sa = aBase + (buf) * ABUF + (a_mtL * 4) * 512 + a_lane * 16;       \
    _Pragma("unroll")                                                            \
    for (int _c = 0; _c < 4; _c++)                                               \
        CP_ASYNC16(_sa + _c * 512, (const char*)(_ga + _c * 128 + a_lane * 4));  \
    const uint32_t* _gb = d_Bf + (((size_t)(n0 / 8 + b_ntL) * KS16 + _ks0) * 64); \
    uint32_t _sb = bBase + (buf) * BBUF + (b_ntL * 4) * 256 + b_in * 16;         \
    _Pragma("unroll")                                                            \
    for (int _c = 0; _c < 4; _c++)                                               \
        CP_ASYNC16(_sb + _c * 256, (const char*)(_gb + _c * 64 + b_in * 4));     \
} while (0)

    LOAD_TILE(0, 0);
    CP_COMMIT();

    for (int it = 0; it < FC_ITERS; it++) {
        const int buf = it & 1;
        if (it + 1 < FC_ITERS) LOAD_TILE(it + 1, buf ^ 1);
        CP_COMMIT();
        CP_WAIT1();
        __syncthreads();

        const uint32_t aOff = aBase + buf * ABUF;
        const uint32_t bOff = bBase + buf * BBUF;
#pragma unroll
        for (int ks = 0; ks < 4; ks++) {
            uint32_t a[4][4];
#pragma unroll
            for (int mt = 0; mt < 4; mt++) {
                uint32_t addr = aOff + ((mtW + mt) * 4 + ks) * 512 + lane * 16;
                asm volatile("ld.shared.v4.b32 {%0,%1,%2,%3}, [%4];"
                             : "=r"(a[mt][0]), "=r"(a[mt][1]),
                               "=r"(a[mt][2]), "=r"(a[mt][3]) : "r"(addr));
            }
            uint32_t b[4][2];
#pragma unroll
            for (int nt = 0; nt < 4; nt++) {
                uint32_t addr = bOff + ((ntW + nt) * 4 + ks) * 256 + lane * 8;
                asm volatile("ld.shared.v2.b32 {%0,%1}, [%2];"
                             : "=r"(b[nt][0]), "=r"(b[nt][1]) : "r"(addr));
            }
#pragma unroll
            for (int mt = 0; mt < 4; mt++)
#pragma unroll
                for (int nt = 0; nt < 4; nt++)
                    mma_f16(acc[mt][nt], a[mt], b[nt][0], b[nt][1]);
        }
        __syncthreads();
    }

    const int g   = lane >> 2;
    const int tig = lane & 3;
#pragma unroll
    for (int mt = 0; mt < 4; mt++) {
#pragma unroll
        for (int half = 0; half < 2; half++) {
            int m = m0 + (mtW + mt) * 16 + g + half * 8;
            if (m >= MROWS) continue;
            int bidx = m / TDEC;
            int tt   = m - bidx * TDEC;
            float* orow = out + ((size_t)bidx * 32 + tt + 1) * VOC;
#pragma unroll
            for (int nt = 0; nt < 4; nt++) {
                int n = n0 + (ntW + nt) * 8 + tig * 2;
                float b0 = __ldg(bias + n);
                float b1 = __ldg(bias + n + 1);
                float2 v = make_float2(acc[mt][nt][half * 2 + 0] + b0,
                                       acc[mt][nt][half * 2 + 1] + b1);
                *(float2*)(orow + n) = v;
            }
        }
    }
}

// ---------------- zero out[:, 0, :] ----------------
__global__ void zero_t0_kernel(float* __restrict__ out)
{
    int idx = blockIdx.x * blockDim.x + threadIdx.x;
    const int n4 = BATCH * (VOC / 4);
    if (idx < n4) {
        int b  = idx / (VOC / 4);
        int v4 = idx - b * (VOC / 4);
        ((float4*)(out + (size_t)b * 32 * VOC))[v4] = make_float4(0.f, 0.f, 0.f, 0.f);
    }
}

// ---------------- launch ----------------
extern "C" void kernel_launch(void* const* d_in, const int* in_sizes, int n_in,
                              void* d_out, int out_size)
{
    const int*   src     = (const int*)  d_in[0];
    const int*   tgt     = (const int*)  d_in[1];
    const float* enc_emb = (const float*)d_in[2];
    const float* dec_emb = (const float*)d_in[3];
    const float* enc_Wih = (const float*)d_in[4];
    const float* enc_Whh = (const float*)d_in[5];
    const float* enc_bih = (const float*)d_in[6];
    const float* enc_bhh = (const float*)d_in[7];
    const float* dec_Wih = (const float*)d_in[8];
    const float* dec_Whh = (const float*)d_in[9];
    const float* dec_bih = (const float*)d_in[10];
    const float* dec_bhh = (const float*)d_in[11];
    const float* fc_W    = (const float*)d_in[12];
    const float* fc_b    = (const float*)d_in[13];
    float* out = (float*)d_out;

    static int attr_set = 0;
    if (!attr_set) {
        cudaFuncSetAttribute(fc_mma_kernel,
                             cudaFuncAttributeMaxDynamicSharedMemorySize, FC_SMEM);
        cudaFuncSetAttribute(scan_tc_kernel,
                             cudaFuncAttributeMaxDynamicSharedMemorySize, SCAN_SMEM);
        cudaFuncSetAttribute(xp_mma_kernel,
                             cudaFuncAttributeMaxDynamicSharedMemorySize, XP_SMEM);
        attr_set = 1;
    }

    convWih_frag_kernel<<<(2 * 256 * EKS16 * 32 + 255) / 256, 256>>>(enc_Wih, dec_Wih);
    xp_mma_kernel<<<dim3(16, SENC + TDEC), 256, XP_SMEM>>>(
        src, tgt, enc_emb, dec_emb, enc_bih, enc_bhh, dec_bih, dec_bhh);
    convWhh_frag_kernel<<<(2 * SNBLK * 4 * KS16 * 32 + 255) / 256, 256>>>(enc_Whh, dec_Whh);
    convB_frag_kernel<<<(NT8 * KS16 * 32 + 255) / 256, 256>>>(fc_W);
    scan_tc_kernel<<<SNBLK, 256, SCAN_SMEM>>>();
    convA_frag_kernel<<<((MPAD / 16) * KS16 * 32 + 255) / 256, 256>>>();
    zero_t0_kernel<<<(BATCH * (VOC / 4) + 255) / 256, 256>>>(out);
    fc_mma_kernel<<<dim3(MPAD / 128, VOC / 128), 256, FC_SMEM>>>(fc_b, out);
}

// round 12
// speedup vs baseline: 4.2678x; 1.5434x over previous
#include <cuda_runtime.h>
#include <cuda_fp16.h>
#include <math.h>
#include <stdint.h>

#define BATCH 64
#define SENC  64
#define TDEC  31          // decoder steps = T-1
#define EMB   256
#define HID   512
#define G4    2048        // 4*H
#define VOC   32000
#define SNBLK 64          // persistent scan blocks (all resident)
#define MROWS (BATCH * TDEC)   // 1984 rows into FC
#define MPAD  2048             // padded FC rows (16 x 128)
#define KS16  (HID / 16)       // 32 k16-steps (FC / scan K)
#define EKS16 (EMB / 16)       // 16 k16-steps (xp K)
#define NT8   (VOC / 8)        // 4000 n8 tiles

// ---------------- scratch (device globals; no allocation) ----------------
__device__ float  d_xp_enc[SENC * BATCH * G4];   // [t][b][g] fp32
__device__ float  d_xp_dec[TDEC * BATCH * G4];
__device__ __half d_hbuf[2][BATCH * HID];        // ping-pong h (fp16)
__device__ __half d_hseq[MROWS * HID];           // decoder outputs (fp16)
__device__ unsigned d_bar_ctr = 0;               // monotonic arrival counter

// fp16 fragment-major operands (packed half2 in uint32)
__device__ uint32_t d_Af[(MPAD / 16) * KS16 * 32 * 4];   // A: [mt][ks][lane][4]
__device__ uint32_t d_Bf[NT8 * KS16 * 32 * 2];           // B: [nt8][ks][lane][2]
__device__ uint32_t d_WihF[2 * 256 * EKS16 * 32 * 2];    // [layer][n8][ks][lane][2]
__device__ uint32_t d_WhhF[2 * SNBLK * 4 * KS16 * 32 * 2]; // [layer][bid][nt][ks][lane][2]

// ---------------- helpers ----------------
__device__ __forceinline__ uint32_t smem_u32(const void* p) {
    uint32_t a;
    asm("{ .reg .u64 t; cvta.to.shared.u64 t, %1; cvt.u32.u64 %0, t; }"
        : "=r"(a) : "l"(p));
    return a;
}
#define CP_ASYNC16(dst, src) \
    asm volatile("cp.async.cg.shared.global [%0], [%1], 16;" \
                 :: "r"(dst), "l"(src) : "memory")
#define CP_COMMIT() asm volatile("cp.async.commit_group;" ::: "memory")
#define CP_WAIT1()  asm volatile("cp.async.wait_group 1;" ::: "memory")
#define CP_WAITN(n) asm volatile("cp.async.wait_group %0;" :: "n"(n) : "memory")

__device__ __forceinline__ uint32_t packh2(float x, float y) {
    __half2 h = __floats2half2_rn(x, y);
    return *(uint32_t*)&h;
}
__device__ __forceinline__ void mma_f16(float* c, const uint32_t* a,
                                        uint32_t b0, uint32_t b1)
{
    asm volatile("mma.sync.aligned.m16n8k16.row.col.f32.f16.f16.f32 "
                 "{%0,%1,%2,%3}, {%4,%5,%6,%7}, {%8,%9}, {%0,%1,%2,%3};"
                 : "+f"(c[0]), "+f"(c[1]), "+f"(c[2]), "+f"(c[3])
                 : "r"(a[0]), "r"(a[1]), "r"(a[2]), "r"(a[3]), "r"(b0), "r"(b1));
}

// ---------------- grid barrier: monotonic counter, spin (no sleep) ----------------
// All SNBLK blocks arrive via red.add (no return value), then every block
// self-releases by polling until ctr >= target. No reset store, no designated
// releaser on the critical path. Ctr zeroed by convWhh kernel each launch.
__device__ __forceinline__ void global_barrier(unsigned target)
{
    __syncthreads();
    if (threadIdx.x == 0) {
        __threadfence();
        asm volatile("red.release.gpu.global.add.u32 [%0], 1;"
                     :: "l"(&d_bar_ctr) : "memory");
        unsigned v;
        do {
            asm volatile("ld.acquire.gpu.global.u32 %0, [%1];"
                         : "=r"(v) : "l"(&d_bar_ctr) : "memory");
        } while (v < target);
        __threadfence();
    }
    __syncthreads();
}

__device__ __forceinline__ float sigm(float x) { return 1.0f / (1.0f + expf(-x)); }

// ---------------- Wih -> fp16 fragments ----------------
__global__ __launch_bounds__(256) void convWih_frag_kernel(
    const float* __restrict__ encWih, const float* __restrict__ decWih)
{
    int idx = blockIdx.x * 256 + threadIdx.x;     // one uint2
    if (idx >= 2 * 256 * EKS16 * 32) return;
    int lane  = idx & 31;
    int ks    = (idx >> 5) & (EKS16 - 1);
    int nt    = (idx >> 9) & 255;
    int layer = idx >> 17;
    int g = lane >> 2, tig = lane & 3;
    const float* W = layer ? decWih : encWih;
    const float* row = W + (size_t)(nt * 8 + g) * EMB + ks * 16 + tig * 2;
    ((uint2*)d_WihF)[idx] = make_uint2(packh2(row[0], row[1]),
                                      packh2(row[8], row[9]));
}

// ---------------- xp via fp16 mma ----------------
#define XPP 264                     // smem pitch in halves (132 words ≡ 4 mod 32)
#define XP_SMEM (64 * XPP * 2)      // 33792 B

__global__ __launch_bounds__(256, 2) void xp_mma_kernel(
    const int*   __restrict__ src,  const int* __restrict__ tgt,
    const float* __restrict__ enc_emb, const float* __restrict__ dec_emb,
    const float* __restrict__ enc_bih, const float* __restrict__ enc_bhh,
    const float* __restrict__ dec_bih, const float* __restrict__ dec_bhh)
{
    extern __shared__ __half a_s[];

    const int tid  = threadIdx.x;
    const int wid  = tid >> 5;
    const int lane = tid & 31;
    const int n0   = blockIdx.x * 128;
    const int t    = blockIdx.y;

    const int*   toks; const float* emb; const float* bi; const float* bh;
    const uint32_t* WF; float* xp; int tloc, tstride;
    if (t < SENC) {
        toks = src; emb = enc_emb; bi = enc_bih; bh = enc_bhh;
        WF = d_WihF; xp = d_xp_enc + (size_t)t * BATCH * G4;
        tloc = t; tstride = SENC;
    } else {
        toks = tgt; emb = dec_emb; bi = dec_bih; bh = dec_bhh;
        WF = d_WihF + 256 * EKS16 * 32 * 2;
        xp = d_xp_dec + (size_t)(t - SENC) * BATCH * G4;
        tloc = t - SENC; tstride = 32;
    }

    // gather 64 emb rows -> fp16 smem (8192 half2)
#pragma unroll
    for (int i = 0; i < 32; i++) {
        int q  = tid + i * 256;
        int r  = q >> 7;
        int c2 = q & 127;
        int tok = __ldg(toks + r * tstride + tloc);
        float2 v = __ldg((const float2*)(emb + (size_t)tok * EMB + c2 * 2));
        *(uint32_t*)&a_s[r * XPP + c2 * 2] = packh2(v.x, v.y);
    }
    __syncthreads();

    const int mt = wid >> 1;
    const int nh = wid & 1;
    const int g  = lane >> 2, tig = lane & 3;

    float acc[8][4];
#pragma unroll
    for (int nt = 0; nt < 8; nt++)
#pragma unroll
        for (int r = 0; r < 4; r++) acc[nt][r] = 0.0f;

    const int n8base = n0 / 8 + nh * 8;
    const __half* ap = &a_s[(mt * 16 + g) * XPP + tig * 2];

    for (int ks = 0; ks < EKS16; ks++) {
        uint32_t a[4];
        a[0] = *(const uint32_t*)(ap + ks * 16);
        a[2] = *(const uint32_t*)(ap + ks * 16 + 8);
        a[1] = *(const uint32_t*)(ap + ks * 16 + 8 * XPP);
        a[3] = *(const uint32_t*)(ap + ks * 16 + 8 * XPP + 8);
#pragma unroll
        for (int nt = 0; nt < 8; nt++) {
            uint2 b = __ldg((const uint2*)(WF +
                      (((size_t)(n8base + nt) * EKS16 + ks) * 32 + lane) * 2));
            mma_f16(acc[nt], a, b.x, b.y);
        }
    }

#pragma unroll
    for (int nt = 0; nt < 8; nt++) {
        int n = (n8base + nt) * 8 + tig * 2;
        float b0 = __ldg(bi + n) + __ldg(bh + n);
        float b1 = __ldg(bi + n + 1) + __ldg(bh + n + 1);
        int r0 = mt * 16 + g;
        *(float2*)(xp + (size_t)r0 * G4 + n) =
            make_float2(acc[nt][0] + b0, acc[nt][1] + b1);
        *(float2*)(xp + (size_t)(r0 + 8) * G4 + n) =
            make_float2(acc[nt][2] + b0, acc[nt][3] + b1);
    }
}

// ---------------- Whh -> gate-permuted fp16 fragments (also resets barrier ctr) ----------------
__global__ __launch_bounds__(256) void convWhh_frag_kernel(
    const float* __restrict__ encWhh, const float* __restrict__ decWhh)
{
    if (blockIdx.x == 0 && threadIdx.x == 0) d_bar_ctr = 0;   // per-launch reset

    int idx = blockIdx.x * 256 + threadIdx.x;     // one uint2
    if (idx >= 2 * SNBLK * 4 * KS16 * 32) return;
    int lane  = idx & 31;
    int ks    = (idx >> 5) & (KS16 - 1);
    int nt    = (idx >> 10) & 3;
    int bid   = (idx >> 12) & 63;
    int layer = idx >> 18;

    int g = lane >> 2, tig = lane & 3;
    int nn   = nt * 8 + g;
    int j    = bid * 8 + (nn >> 2);
    int gate = nn & 3;
    const float* W = layer ? decWhh : encWhh;
    const float* row = W + (size_t)(gate * HID + j) * HID + ks * 16 + tig * 2;
    ((uint2*)d_WhhF)[idx] = make_uint2(packh2(row[0], row[1]),
                                      packh2(row[8], row[9]));
}

// ---------------- persistent LSTM scan, fp16 tensor cores, 64 blocks ----------------
#define HPB   1040                                   // h row pitch bytes (260 words ≡ 4 mod 32)
#define WFU   (4 * KS16 * 32 * 2)                    // 8192 u32 = 32 KB
#define SCAN_SMEM (WFU * 4 + 64 * HPB)               // 99328 B

__global__ __launch_bounds__(256, 1) void scan_tc_kernel()
{
    extern __shared__ char scm[];
    uint32_t* wf = (uint32_t*)scm;                   // Whh frags
    char*     hs = scm + WFU * 4;                    // [64 rows][HPB]
    const uint32_t hBase = smem_u32(hs);

    const int tid  = threadIdx.x;
    const int bid  = blockIdx.x;
    const int wid  = tid >> 5;
    const int lane = tid & 31;
    const int mt   = wid & 3;
    const int ntp  = (wid >> 2) * 2;
    const int g    = lane >> 2;
    const int tig  = lane & 3;
    const int odd  = lane & 1;

    const int row0 = mt * 16 + g;
    const int myb  = mt * 16 + g + odd * 8;
    const int j0   = bid * 8 + ntp * 2 + (tig >> 1);
    const int j1   = j0 + 2;

    // h0 = 0
#pragma unroll
    for (int i = 0; i < 2; i++) {
        int e = tid + i * 256;
        d_hbuf[0][(e >> 3) * HID + bid * 8 + (e & 7)] = __float2half(0.0f);
    }
    float c0 = 0.0f, c1 = 0.0f;

    {   // encoder Whh frags: 8192 u32 = 2048 uint4
        const uint4* s = (const uint4*)(d_WhhF + (size_t)bid * WFU);
#pragma unroll
        for (int i = 0; i < 8; i++)
            ((uint4*)wf)[tid + i * 256] = s[tid + i * 256];
    }
    __syncthreads();

    unsigned bar_target = SNBLK;
    global_barrier(bar_target); bar_target += SNBLK;   // h0 visible everywhere

    for (int step = 0; step < SENC + TDEC; step++) {
        if (step == SENC) {
            __syncthreads();
            const uint4* s = (const uint4*)(d_WhhF + (size_t)(SNBLK + bid) * WFU);
#pragma unroll
            for (int i = 0; i < 8; i++)
                ((uint4*)wf)[tid + i * 256] = s[tid + i * 256];
            __syncthreads();
        }

        const __half* __restrict__ hprev = d_hbuf[step & 1];
        __half*       __restrict__ hnext = d_hbuf[(step & 1) ^ 1];
        const float*  __restrict__ xp_t  =
            (step < SENC) ? (d_xp_enc + (size_t)step * BATCH * G4)
                          : (d_xp_dec + (size_t)(step - SENC) * BATCH * G4);

        // prefetch xp gate values (independent of h)
        const float* xb0 = xp_t + (size_t)myb * G4 + j0;
        const float* xb1 = xp_t + (size_t)myb * G4 + j1;
        float xi0 = __ldcg(xb0),        xf0 = __ldcg(xb0 + 512);
        float xg0 = __ldcg(xb0 + 1024), xo0 = __ldcg(xb0 + 1536);
        float xi1 = __ldcg(xb1),        xf1 = __ldcg(xb1 + 512);
        float xg1 = __ldcg(xb1 + 1024), xo1 = __ldcg(xb1 + 1536);

        // stage h (fp16) in 2 chunks of 256 cols (512 B/row) via cp.async
#pragma unroll
        for (int ch = 0; ch < 2; ch++) {
#pragma unroll
            for (int i = 0; i < 8; i++) {
                int q  = tid + i * 256;              // 2048 16B-chunks per col-chunk
                int r  = q >> 5;
                int cb = (q & 31) * 16;
                CP_ASYNC16(hBase + r * HPB + ch * 512 + cb,
                           (const char*)hprev + (size_t)r * 1024 + ch * 512 + cb);
            }
            CP_COMMIT();
        }

        float acc[2][4];
#pragma unroll
        for (int u = 0; u < 2; u++)
#pragma unroll
            for (int r = 0; r < 4; r++) acc[u][r] = 0.0f;

#pragma unroll
        for (int ch = 0; ch < 2; ch++) {
            if (ch == 0) CP_WAITN(1);
            else CP_WAITN(0);
            __syncthreads();

            const char* ap = hs + row0 * HPB + ch * 512 + tig * 4;
            const uint32_t* bp0 = wf + ((ntp * KS16 + ch * 16) * 32 + lane) * 2;
            const uint32_t* bp1 = wf + (((ntp + 1) * KS16 + ch * 16) * 32 + lane) * 2;
#pragma unroll
            for (int k2 = 0; k2 < 16; k2++) {       // 16 k16-steps per chunk
                uint32_t a[4];
                a[0] = *(const uint32_t*)(ap + k2 * 32);
                a[2] = *(const uint32_t*)(ap + k2 * 32 + 16);
                a[1] = *(const uint32_t*)(ap + k2 * 32 + 8 * HPB);
                a[3] = *(const uint32_t*)(ap + k2 * 32 + 8 * HPB + 16);
                uint2 b0 = *(const uint2*)(bp0 + k2 * 64);
                uint2 b1 = *(const uint2*)(bp1 + k2 * 64);
                mma_f16(acc[0], a, b0.x, b0.y);
                mma_f16(acc[1], a, b1.x, b1.y);
            }
        }

        // gate reassembly + pointwise
#pragma unroll
        for (int u = 0; u < 2; u++) {
            float* a = acc[u];
            float o0 = __shfl_xor_sync(0xFFFFFFFFu, a[0], 1);
            float o1 = __shfl_xor_sync(0xFFFFFFFFu, a[1], 1);
            float o2 = __shfl_xor_sync(0xFFFFFFFFu, a[2], 1);
            float o3 = __shfl_xor_sync(0xFFFFFFFFu, a[3], 1);
            float pi, pf, pg, po;
            if (!odd) { pi = a[0]; pf = a[1]; pg = o0;   po = o1;   }
            else      { pi = o2;   pf = o3;   pg = a[2]; po = a[3]; }

            if (u == 0) { pi += xi0; pf += xf0; pg += xg0; po += xo0; }
            else        { pi += xi1; pf += xf1; pg += xg1; po += xo1; }

            float& cc = (u == 0) ? c0 : c1;
            cc = sigm(pf) * cc + sigm(pi) * tanhf(pg);
            __half hr = __float2half_rn(sigm(po) * tanhf(cc));

            int j = (u == 0) ? j0 : j1;
            __stcg((short*)&hnext[(size_t)myb * HID + j], *(short*)&hr);
            if (step >= SENC) {
                int t = step - SENC;
                d_hseq[((size_t)myb * TDEC + t) * HID + j] = hr;
            }
        }
        global_barrier(bar_target); bar_target += SNBLK;
    }
}

// ---------------- fragment gathers for the FC ----------------
__global__ __launch_bounds__(256) void convA_frag_kernel()
{
    int idx = blockIdx.x * 256 + threadIdx.x;        // one uint4
    const int total = (MPAD / 16) * KS16 * 32;
    if (idx >= total) return;
    int lane = idx & 31;
    int ks   = (idx >> 5) & (KS16 - 1);
    int mt   = idx / (32 * KS16);
    int g    = lane >> 2, tig = lane & 3;
    int m0   = mt * 16 + g;
    int k0   = ks * 16 + tig * 2;

    uint32_t a0 = 0, a1 = 0, a2 = 0, a3 = 0;
    if (m0 < MROWS) {
        a0 = *(const uint32_t*)&d_hseq[(size_t)m0 * HID + k0];
        a2 = *(const uint32_t*)&d_hseq[(size_t)m0 * HID + k0 + 8];
    }
    if (m0 + 8 < MROWS) {
        a1 = *(const uint32_t*)&d_hseq[(size_t)(m0 + 8) * HID + k0];
        a3 = *(const uint32_t*)&d_hseq[(size_t)(m0 + 8) * HID + k0 + 8];
    }
    ((uint4*)d_Af)[idx] = make_uint4(a0, a1, a2, a3);
}

__global__ __launch_bounds__(256) void convB_frag_kernel(const float* __restrict__ W)
{
    int idx = blockIdx.x * 256 + threadIdx.x;        // one uint2
    const int total = NT8 * KS16 * 32;
    if (idx >= total) return;
    int lane = idx & 31;
    int ks   = (idx >> 5) & (KS16 - 1);
    int nt   = idx / (32 * KS16);
    int g    = lane >> 2, tig = lane & 3;
    const float* row = W + (size_t)(nt * 8 + g) * HID + ks * 16 + tig * 2;
    ((uint2*)d_Bf)[idx] = make_uint2(packh2(row[0], row[1]),
                                    packh2(row[8], row[9]));
}

// ---------------- FC via fp16 mma.sync ----------------
#define FC_ITERS 8
#define ABUF 16384
#define BBUF 16384
#define FC_SMEM (2 * (ABUF + BBUF))   // 64 KB

__global__ __launch_bounds__(256, 2) void fc_mma_kernel(
    const float* __restrict__ bias, float* __restrict__ out)
{
    extern __shared__ char smem[];
    const uint32_t aBase = smem_u32(smem);
    const uint32_t bBase = aBase + 2 * ABUF;

    const int tid  = threadIdx.x;
    const int wid  = tid >> 5;
    const int lane = tid & 31;
    const int m0   = blockIdx.x * 128;     // fast dim: m-tiles share B via L2
    const int n0   = blockIdx.y * 128;

    const int mtW  = (wid >> 2) * 4;
    const int ntW  = (wid & 3) * 4;

    float acc[4][4][4];
#pragma unroll
    for (int mt = 0; mt < 4; mt++)
#pragma unroll
        for (int nt = 0; nt < 4; nt++)
#pragma unroll
            for (int r = 0; r < 4; r++) acc[mt][nt][r] = 0.0f;

    const int a_mtL  = tid >> 5;
    const int a_lane = tid & 31;
    const int b_ntL  = tid >> 4;
    const int b_in   = tid & 15;

#define LOAD_TILE(it, buf) do {                                                  \
    int _ks0 = (it) * 4;                                                         \
    const uint32_t* _ga = d_Af + (((size_t)(m0 / 16 + a_mtL) * KS16 + _ks0) * 128); \
    uint32_t _sa = aBase + (buf) * ABUF + (a_mtL * 4) * 512 + a_lane * 16;       \
    _Pragma("unroll")                                                            \
    for (int _c = 0; _c < 4; _c++)                                               \
        CP_ASYNC16(_sa + _c * 512, (const char*)(_ga + _c * 128 + a_lane * 4));  \
    const uint32_t* _gb = d_Bf + (((size_t)(n0 / 8 + b_ntL) * KS16 + _ks0) * 64); \
    uint32_t _sb = bBase + (buf) * BBUF + (b_ntL * 4) * 256 + b_in * 16;         \
    _Pragma("unroll")                                                            \
    for (int _c = 0; _c < 4; _c++)                                               \
        CP_ASYNC16(_sb + _c * 256, (const char*)(_gb + _c * 64 + b_in * 4));     \
} while (0)

    LOAD_TILE(0, 0);
    CP_COMMIT();

    for (int it = 0; it < FC_ITERS; it++) {
        const int buf = it & 1;
        if (it + 1 < FC_ITERS) LOAD_TILE(it + 1, buf ^ 1);
        CP_COMMIT();
        CP_WAIT1();
        __syncthreads();

        const uint32_t aOff = aBase + buf * ABUF;
        const uint32_t bOff = bBase + buf * BBUF;
#pragma unroll
        for (int ks = 0; ks < 4; ks++) {
            uint32_t a[4][4];
#pragma unroll
            for (int mt = 0; mt < 4; mt++) {
                uint32_t addr = aOff + ((mtW + mt) * 4 + ks) * 512 + lane * 16;
                asm volatile("ld.shared.v4.b32 {%0,%1,%2,%3}, [%4];"
                             : "=r"(a[mt][0]), "=r"(a[mt][1]),
                               "=r"(a[mt][2]), "=r"(a[mt][3]) : "r"(addr));
            }
            uint32_t b[4][2];
#pragma unroll
            for (int nt = 0; nt < 4; nt++) {
                uint32_t addr = bOff + ((ntW + nt) * 4 + ks) * 256 + lane * 8;
                asm volatile("ld.shared.v2.b32 {%0,%1}, [%2];"
                             : "=r"(b[nt][0]), "=r"(b[nt][1]) : "r"(addr));
            }
#pragma unroll
            for (int mt = 0; mt < 4; mt++)
#pragma unroll
                for (int nt = 0; nt < 4; nt++)
                    mma_f16(acc[mt][nt], a[mt], b[nt][0], b[nt][1]);
        }
        __syncthreads();
    }

    const int g   = lane >> 2;
    const int tig = lane & 3;
#pragma unroll
    for (int mt = 0; mt < 4; mt++) {
#pragma unroll
        for (int half = 0; half < 2; half++) {
            int m = m0 + (mtW + mt) * 16 + g + half * 8;
            if (m >= MROWS) continue;
            int bidx = m / TDEC;
            int tt   = m - bidx * TDEC;
            float* orow = out + ((size_t)bidx * 32 + tt + 1) * VOC;
#pragma unroll
            for (int nt = 0; nt < 4; nt++) {
                int n = n0 + (ntW + nt) * 8 + tig * 2;
                float b0 = __ldg(bias + n);
                float b1 = __ldg(bias + n + 1);
                float2 v = make_float2(acc[mt][nt][half * 2 + 0] + b0,
                                       acc[mt][nt][half * 2 + 1] + b1);
                *(float2*)(orow + n) = v;
            }
        }
    }
}

// ---------------- zero out[:, 0, :] ----------------
__global__ void zero_t0_kernel(float* __restrict__ out)
{
    int idx = blockIdx.x * blockDim.x + threadIdx.x;
    const int n4 = BATCH * (VOC / 4);
    if (idx < n4) {
        int b  = idx / (VOC / 4);
        int v4 = idx - b * (VOC / 4);
        ((float4*)(out + (size_t)b * 32 * VOC))[v4] = make_float4(0.f, 0.f, 0.f, 0.f);
    }
}

// ---------------- launch ----------------
// Order puts scan_tc_kernel at launch slot 4 so the ncu window captures it.
extern "C" void kernel_launch(void* const* d_in, const int* in_sizes, int n_in,
                              void* d_out, int out_size)
{
    const int*   src     = (const int*)  d_in[0];
    const int*   tgt     = (const int*)  d_in[1];
    const float* enc_emb = (const float*)d_in[2];
    const float* dec_emb = (const float*)d_in[3];
    const float* enc_Wih = (const float*)d_in[4];
    const float* enc_Whh = (const float*)d_in[5];
    const float* enc_bih = (const float*)d_in[6];
    const float* enc_bhh = (const float*)d_in[7];
    const float* dec_Wih = (const float*)d_in[8];
    const float* dec_Whh = (const float*)d_in[9];
    const float* dec_bih = (const float*)d_in[10];
    const float* dec_bhh = (const float*)d_in[11];
    const float* fc_W    = (const float*)d_in[12];
    const float* fc_b    = (const float*)d_in[13];
    float* out = (float*)d_out;

    static int attr_set = 0;
    if (!attr_set) {
        cudaFuncSetAttribute(fc_mma_kernel,
                             cudaFuncAttributeMaxDynamicSharedMemorySize, FC_SMEM);
        cudaFuncSetAttribute(scan_tc_kernel,
                             cudaFuncAttributeMaxDynamicSharedMemorySize, SCAN_SMEM);
        cudaFuncSetAttribute(xp_mma_kernel,
                             cudaFuncAttributeMaxDynamicSharedMemorySize, XP_SMEM);
        attr_set = 1;
    }

    convWih_frag_kernel<<<(2 * 256 * EKS16 * 32 + 255) / 256, 256>>>(enc_Wih, dec_Wih);   // 1
    xp_mma_kernel<<<dim3(16, SENC + TDEC), 256, XP_SMEM>>>(
        src, tgt, enc_emb, dec_emb, enc_bih, enc_bhh, dec_bih, dec_bhh);                  // 2
    convWhh_frag_kernel<<<(2 * SNBLK * 4 * KS16 * 32 + 255) / 256, 256>>>(enc_Whh, dec_Whh); // 3 (+ ctr reset)
    scan_tc_kernel<<<SNBLK, 256, SCAN_SMEM>>>();                                          // 4 <- ncu window
    convB_frag_kernel<<<(NT8 * KS16 * 32 + 255) / 256, 256>>>(fc_W);                      // 5
    convA_frag_kernel<<<((MPAD / 16) * KS16 * 32 + 255) / 256, 256>>>();                  // 6
    zero_t0_kernel<<<(BATCH * (VOC / 4) + 255) / 256, 256>>>(out);                        // 7
    fc_mma_kernel<<<dim3(MPAD / 128, VOC / 128), 256, FC_SMEM>>>(fc_b, out);              // 8
}

// round 13
// speedup vs baseline: 5.2371x; 1.2271x over previous
#include <cuda_runtime.h>
#include <cuda_fp16.h>
#include <math.h>
#include <stdint.h>

#define BATCH 64
#define SENC  64
#define TDEC  31          // decoder steps = T-1
#define EMB   256
#define HID   512
#define G4    2048        // 4*H
#define VOC   32000
#define SNBLK 64          // persistent scan blocks (all resident)
#define NSTEP (SENC + TDEC)
#define MROWS (BATCH * TDEC)   // 1984 rows into FC
#define MPAD  2048             // padded FC rows (16 x 128)
#define KS16  (HID / 16)       // 32 k16-steps (FC / scan K)
#define EKS16 (EMB / 16)       // 16 k16-steps (xp K)
#define NT8   (VOC / 8)        // 4000 n8 tiles

// ---------------- scratch (device globals; no allocation) ----------------
__device__ float  d_xp_enc[SENC * BATCH * G4];   // [t][b][g] fp32
__device__ float  d_xp_dec[TDEC * BATCH * G4];
__device__ __half d_hbuf[2][BATCH * HID];        // ping-pong h (fp16)
__device__ __half d_hseq[MROWS * HID];           // decoder outputs (fp16)
__device__ unsigned d_bar_ctr = 0;               // monotonic arrival counter

// fp16 fragment-major operands (packed half2 in uint32)
__device__ uint32_t d_Af[(MPAD / 16) * KS16 * 32 * 4];   // A: [mt][ks][lane][4]
__device__ uint32_t d_Bf[NT8 * KS16 * 32 * 2];           // B: [nt8][ks][lane][2]
__device__ uint32_t d_WihF[2 * 256 * EKS16 * 32 * 2];    // [layer][n8][ks][lane][2]
__device__ uint32_t d_WhhF[2 * SNBLK * 4 * KS16 * 32 * 2]; // [layer][bid][nt][ks][lane][2]

// ---------------- helpers ----------------
__device__ __forceinline__ uint32_t smem_u32(const void* p) {
    uint32_t a;
    asm("{ .reg .u64 t; cvta.to.shared.u64 t, %1; cvt.u32.u64 %0, t; }"
        : "=r"(a) : "l"(p));
    return a;
}
#define CP_ASYNC16(dst, src) \
    asm volatile("cp.async.cg.shared.global [%0], [%1], 16;" \
                 :: "r"(dst), "l"(src) : "memory")
#define CP_COMMIT() asm volatile("cp.async.commit_group;" ::: "memory")
#define CP_WAIT1()  asm volatile("cp.async.wait_group 1;" ::: "memory")
#define CP_WAITN(n) asm volatile("cp.async.wait_group %0;" :: "n"(n) : "memory")

__device__ __forceinline__ uint32_t packh2(float x, float y) {
    __half2 h = __floats2half2_rn(x, y);
    return *(uint32_t*)&h;
}
__device__ __forceinline__ void mma_f16(float* c, const uint32_t* a,
                                        uint32_t b0, uint32_t b1)
{
    asm volatile("mma.sync.aligned.m16n8k16.row.col.f32.f16.f16.f32 "
                 "{%0,%1,%2,%3}, {%4,%5,%6,%7}, {%8,%9}, {%0,%1,%2,%3};"
                 : "+f"(c[0]), "+f"(c[1]), "+f"(c[2]), "+f"(c[3])
                 : "r"(a[0]), "r"(a[1]), "r"(a[2]), "r"(a[3]), "r"(b0), "r"(b1));
}

__device__ __forceinline__ void bar_red_release() {
    asm volatile("red.release.gpu.global.add.u32 [%0], 1;"
                 :: "l"(&d_bar_ctr) : "memory");
}
__device__ __forceinline__ void bar_poll(unsigned target) {
    unsigned v;
    do {
        asm volatile("ld.acquire.gpu.global.u32 %0, [%1];"
                     : "=r"(v) : "l"(&d_bar_ctr) : "memory");
    } while (v < target);
}

// fast pointwise (MUFU-based; ~2^-21 rel err)
__device__ __forceinline__ float sigm(float x) {
    return __fdividef(1.0f, 1.0f + __expf(-x));
}
__device__ __forceinline__ float tanh_fast(float x) {
    return 1.0f - __fdividef(2.0f, __expf(2.0f * x) + 1.0f);
}

// ---------------- Wih -> fp16 fragments ----------------
__global__ __launch_bounds__(256) void convWih_frag_kernel(
    const float* __restrict__ encWih, const float* __restrict__ decWih)
{
    int idx = blockIdx.x * 256 + threadIdx.x;     // one uint2
    if (idx >= 2 * 256 * EKS16 * 32) return;
    int lane  = idx & 31;
    int ks    = (idx >> 5) & (EKS16 - 1);
    int nt    = (idx >> 9) & 255;
    int layer = idx >> 17;
    int g = lane >> 2, tig = lane & 3;
    const float* W = layer ? decWih : encWih;
    const float* row = W + (size_t)(nt * 8 + g) * EMB + ks * 16 + tig * 2;
    ((uint2*)d_WihF)[idx] = make_uint2(packh2(row[0], row[1]),
                                      packh2(row[8], row[9]));
}

// ---------------- xp via fp16 mma ----------------
#define XPP 264                     // smem pitch in halves
#define XP_SMEM (64 * XPP * 2)      // 33792 B

__global__ __launch_bounds__(256, 2) void xp_mma_kernel(
    const int*   __restrict__ src,  const int* __restrict__ tgt,
    const float* __restrict__ enc_emb, const float* __restrict__ dec_emb,
    const float* __restrict__ enc_bih, const float* __restrict__ enc_bhh,
    const float* __restrict__ dec_bih, const float* __restrict__ dec_bhh)
{
    extern __shared__ __half a_s[];

    const int tid  = threadIdx.x;
    const int wid  = tid >> 5;
    const int lane = tid & 31;
    const int n0   = blockIdx.x * 128;
    const int t    = blockIdx.y;

    const int*   toks; const float* emb; const float* bi; const float* bh;
    const uint32_t* WF; float* xp; int tloc, tstride;
    if (t < SENC) {
        toks = src; emb = enc_emb; bi = enc_bih; bh = enc_bhh;
        WF = d_WihF; xp = d_xp_enc + (size_t)t * BATCH * G4;
        tloc = t; tstride = SENC;
    } else {
        toks = tgt; emb = dec_emb; bi = dec_bih; bh = dec_bhh;
        WF = d_WihF + 256 * EKS16 * 32 * 2;
        xp = d_xp_dec + (size_t)(t - SENC) * BATCH * G4;
        tloc = t - SENC; tstride = 32;
    }

    // gather 64 emb rows -> fp16 smem (8192 half2)
#pragma unroll
    for (int i = 0; i < 32; i++) {
        int q  = tid + i * 256;
        int r  = q >> 7;
        int c2 = q & 127;
        int tok = __ldg(toks + r * tstride + tloc);
        float2 v = __ldg((const float2*)(emb + (size_t)tok * EMB + c2 * 2));
        *(uint32_t*)&a_s[r * XPP + c2 * 2] = packh2(v.x, v.y);
    }
    __syncthreads();

    const int mt = wid >> 1;
    const int nh = wid & 1;
    const int g  = lane >> 2, tig = lane & 3;

    float acc[8][4];
#pragma unroll
    for (int nt = 0; nt < 8; nt++)
#pragma unroll
        for (int r = 0; r < 4; r++) acc[nt][r] = 0.0f;

    const int n8base = n0 / 8 + nh * 8;
    const __half* ap = &a_s[(mt * 16 + g) * XPP + tig * 2];

    for (int ks = 0; ks < EKS16; ks++) {
        uint32_t a[4];
        a[0] = *(const uint32_t*)(ap + ks * 16);
        a[2] = *(const uint32_t*)(ap + ks * 16 + 8);
        a[1] = *(const uint32_t*)(ap + ks * 16 + 8 * XPP);
        a[3] = *(const uint32_t*)(ap + ks * 16 + 8 * XPP + 8);
#pragma unroll
        for (int nt = 0; nt < 8; nt++) {
            uint2 b = __ldg((const uint2*)(WF +
                      (((size_t)(n8base + nt) * EKS16 + ks) * 32 + lane) * 2));
            mma_f16(acc[nt], a, b.x, b.y);
        }
    }

#pragma unroll
    for (int nt = 0; nt < 8; nt++) {
        int n = (n8base + nt) * 8 + tig * 2;
        float b0 = __ldg(bi + n) + __ldg(bh + n);
        float b1 = __ldg(bi + n + 1) + __ldg(bh + n + 1);
        int r0 = mt * 16 + g;
        *(float2*)(xp + (size_t)r0 * G4 + n) =
            make_float2(acc[nt][0] + b0, acc[nt][1] + b1);
        *(float2*)(xp + (size_t)(r0 + 8) * G4 + n) =
            make_float2(acc[nt][2] + b0, acc[nt][3] + b1);
    }
}

// ---------------- Whh -> gate-permuted fp16 fragments (also resets barrier ctr) ----------------
__global__ __launch_bounds__(256) void convWhh_frag_kernel(
    const float* __restrict__ encWhh, const float* __restrict__ decWhh)
{
    if (blockIdx.x == 0 && threadIdx.x == 0) d_bar_ctr = 0;   // per-launch reset

    int idx = blockIdx.x * 256 + threadIdx.x;     // one uint2
    if (idx >= 2 * SNBLK * 4 * KS16 * 32) return;
    int lane  = idx & 31;
    int ks    = (idx >> 5) & (KS16 - 1);
    int nt    = (idx >> 10) & 3;
    int bid   = (idx >> 12) & 63;
    int layer = idx >> 18;

    int g = lane >> 2, tig = lane & 3;
    int nn   = nt * 8 + g;
    int j    = bid * 8 + (nn >> 2);
    int gate = nn & 3;
    const float* W = layer ? decWhh : encWhh;
    const float* row = W + (size_t)(gate * HID + j) * HID + ks * 16 + tig * 2;
    ((uint2*)d_WhhF)[idx] = make_uint2(packh2(row[0], row[1]),
                                      packh2(row[8], row[9]));
}

// ---------------- persistent LSTM scan, fp16 tensor cores, 64 blocks ----------------
#define HPB   1040                                   // h row pitch bytes
#define WFU   (4 * KS16 * 32 * 2)                    // 8192 u32 = 32 KB per layer
#define SCAN_SMEM (2 * WFU * 4 + 64 * HPB)           // 132096 B (both layers resident)

__global__ __launch_bounds__(256, 1) void scan_tc_kernel()
{
    extern __shared__ char scm[];
    uint32_t* wf = (uint32_t*)scm;                   // [2 layers] Whh frags
    char*     hs = scm + 2 * WFU * 4;                // [64 rows][HPB]
    const uint32_t hBase = smem_u32(hs);

    const int tid  = threadIdx.x;
    const int bid  = blockIdx.x;
    const int wid  = tid >> 5;
    const int lane = tid & 31;
    const int mt   = wid & 3;
    const int ntp  = (wid >> 2) * 2;
    const int g    = lane >> 2;
    const int tig  = lane & 3;
    const int odd  = lane & 1;

    const int row0 = mt * 16 + g;
    const int myb  = mt * 16 + g + odd * 8;
    const int j0   = bid * 8 + ntp * 2 + (tig >> 1);
    const int j1   = j0 + 2;

    // h0 = 0
#pragma unroll
    for (int i = 0; i < 2; i++) {
        int e = tid + i * 256;
        d_hbuf[0][(e >> 3) * HID + bid * 8 + (e & 7)] = __float2half(0.0f);
    }
    float c0 = 0.0f, c1 = 0.0f;

    {   // BOTH layers' Whh frags upfront: 16384 u32 = 4096 uint4
        const uint4* se = (const uint4*)(d_WhhF + (size_t)bid * WFU);
        const uint4* sd = (const uint4*)(d_WhhF + (size_t)(SNBLK + bid) * WFU);
#pragma unroll
        for (int i = 0; i < 8; i++) {
            ((uint4*)wf)[tid + i * 256]        = se[tid + i * 256];
            ((uint4*)wf)[2048 + tid + i * 256] = sd[tid + i * 256];
        }
    }
    __syncthreads();

    unsigned bar_target = SNBLK;
    // initial barrier: h0 visible everywhere
    if (tid == 0) { bar_red_release(); bar_poll(bar_target); }
    bar_target += SNBLK;
    __syncthreads();

    // prefetch xp for step 0
    float xi0, xf0, xg0, xo0, xi1, xf1, xg1, xo1;
    {
        const float* xp_t = d_xp_enc;
        const float* xb0 = xp_t + (size_t)myb * G4 + j0;
        const float* xb1 = xp_t + (size_t)myb * G4 + j1;
        xi0 = __ldcg(xb0);        xf0 = __ldcg(xb0 + 512);
        xg0 = __ldcg(xb0 + 1024); xo0 = __ldcg(xb0 + 1536);
        xi1 = __ldcg(xb1);        xf1 = __ldcg(xb1 + 512);
        xg1 = __ldcg(xb1 + 1024); xo1 = __ldcg(xb1 + 1536);
    }

    for (int step = 0; step < NSTEP; step++) {
        const __half* __restrict__ hprev = d_hbuf[step & 1];
        __half*       __restrict__ hnext = d_hbuf[(step & 1) ^ 1];
        const uint32_t* wfL = wf + ((step < SENC) ? 0 : WFU);

        // stage h (fp16) in 2 chunks of 256 cols (512 B/row) via cp.async
#pragma unroll
        for (int ch = 0; ch < 2; ch++) {
#pragma unroll
            for (int i = 0; i < 8; i++) {
                int q  = tid + i * 256;              // 2048 16B-chunks per col-chunk
                int r  = q >> 5;
                int cb = (q & 31) * 16;
                CP_ASYNC16(hBase + r * HPB + ch * 512 + cb,
                           (const char*)hprev + (size_t)r * 1024 + ch * 512 + cb);
            }
            CP_COMMIT();
        }

        float acc[2][4];
#pragma unroll
        for (int u = 0; u < 2; u++)
#pragma unroll
            for (int r = 0; r < 4; r++) acc[u][r] = 0.0f;

#pragma unroll
        for (int ch = 0; ch < 2; ch++) {
            if (ch == 0) CP_WAITN(1);
            else CP_WAITN(0);
            __syncthreads();

            const char* ap = hs + row0 * HPB + ch * 512 + tig * 4;
            const uint32_t* bp0 = wfL + ((ntp * KS16 + ch * 16) * 32 + lane) * 2;
            const uint32_t* bp1 = wfL + (((ntp + 1) * KS16 + ch * 16) * 32 + lane) * 2;
#pragma unroll
            for (int k2 = 0; k2 < 16; k2++) {       // 16 k16-steps per chunk
                uint32_t a[4];
                a[0] = *(const uint32_t*)(ap + k2 * 32);
                a[2] = *(const uint32_t*)(ap + k2 * 32 + 16);
                a[1] = *(const uint32_t*)(ap + k2 * 32 + 8 * HPB);
                a[3] = *(const uint32_t*)(ap + k2 * 32 + 8 * HPB + 16);
                uint2 b0 = *(const uint2*)(bp0 + k2 * 64);
                uint2 b1 = *(const uint2*)(bp1 + k2 * 64);
                mma_f16(acc[0], a, b0.x, b0.y);
                mma_f16(acc[1], a, b1.x, b1.y);
            }
        }

        // gate reassembly + pointwise
        __half hr0h, hr1h;
#pragma unroll
        for (int u = 0; u < 2; u++) {
            float* a = acc[u];
            float o0 = __shfl_xor_sync(0xFFFFFFFFu, a[0], 1);
            float o1 = __shfl_xor_sync(0xFFFFFFFFu, a[1], 1);
            float o2 = __shfl_xor_sync(0xFFFFFFFFu, a[2], 1);
            float o3 = __shfl_xor_sync(0xFFFFFFFFu, a[3], 1);
            float pi, pf, pg, po;
            if (!odd) { pi = a[0]; pf = a[1]; pg = o0;   po = o1;   }
            else      { pi = o2;   pf = o3;   pg = a[2]; po = a[3]; }

            if (u == 0) { pi += xi0; pf += xf0; pg += xg0; po += xo0; }
            else        { pi += xi1; pf += xf1; pg += xg1; po += xo1; }

            float& cc = (u == 0) ? c0 : c1;
            cc = sigm(pf) * cc + sigm(pi) * tanh_fast(pg);
            __half hr = __float2half_rn(sigm(po) * tanh_fast(cc));

            int j = (u == 0) ? j0 : j1;
            __stcg((short*)&hnext[(size_t)myb * HID + j], *(short*)&hr);
            if (u == 0) hr0h = hr; else hr1h = hr;
        }

        // ---- barrier with work hidden in the poll shadow ----
        __syncthreads();                      // all hnext stores issued
        if (tid == 0) bar_red_release();      // arrive

        // overlapped work: hseq store + next-step xp prefetch
        if (step >= SENC) {
            int t = step - SENC;
            d_hseq[((size_t)myb * TDEC + t) * HID + j0] = hr0h;
            d_hseq[((size_t)myb * TDEC + t) * HID + j1] = hr1h;
        }
        if (step + 1 < NSTEP) {
            const float* xp_n = (step + 1 < SENC)
                ? (d_xp_enc + (size_t)(step + 1) * BATCH * G4)
                : (d_xp_dec + (size_t)(step + 1 - SENC) * BATCH * G4);
            const float* xb0 = xp_n + (size_t)myb * G4 + j0;
            const float* xb1 = xp_n + (size_t)myb * G4 + j1;
            xi0 = __ldcg(xb0);        xf0 = __ldcg(xb0 + 512);
            xg0 = __ldcg(xb0 + 1024); xo0 = __ldcg(xb0 + 1536);
            xi1 = __ldcg(xb1);        xf1 = __ldcg(xb1 + 512);
            xg1 = __ldcg(xb1 + 1024); xo1 = __ldcg(xb1 + 1536);
        }

        if (tid == 0) bar_poll(bar_target);   // release detection
        bar_target += SNBLK;
        __syncthreads();
    }
}

// ---------------- fragment gathers for the FC ----------------
__global__ __launch_bounds__(256) void convA_frag_kernel()
{
    int idx = blockIdx.x * 256 + threadIdx.x;        // one uint4
    const int total = (MPAD / 16) * KS16 * 32;
    if (idx >= total) return;
    int lane = idx & 31;
    int ks   = (idx >> 5) & (KS16 - 1);
    int mt   = idx / (32 * KS16);
    int g    = lane >> 2, tig = lane & 3;
    int m0   = mt * 16 + g;
    int k0   = ks * 16 + tig * 2;

    uint32_t a0 = 0, a1 = 0, a2 = 0, a3 = 0;
    if (m0 < MROWS) {
        a0 = *(const uint32_t*)&d_hseq[(size_t)m0 * HID + k0];
        a2 = *(const uint32_t*)&d_hseq[(size_t)m0 * HID + k0 + 8];
    }
    if (m0 + 8 < MROWS) {
        a1 = *(const uint32_t*)&d_hseq[(size_t)(m0 + 8) * HID + k0];
        a3 = *(const uint32_t*)&d_hseq[(size_t)(m0 + 8) * HID + k0 + 8];
    }
    ((uint4*)d_Af)[idx] = make_uint4(a0, a1, a2, a3);
}

__global__ __launch_bounds__(256) void convB_frag_kernel(const float* __restrict__ W)
{
    int idx = blockIdx.x * 256 + threadIdx.x;        // one uint2
    const int total = NT8 * KS16 * 32;
    if (idx >= total) return;
    int lane = idx & 31;
    int ks   = (idx >> 5) & (KS16 - 1);
    int nt   = idx / (32 * KS16);
    int g    = lane >> 2, tig = lane & 3;
    const float* row = W + (size_t)(nt * 8 + g) * HID + ks * 16 + tig * 2;
    ((uint2*)d_Bf)[idx] = make_uint2(packh2(row[0], row[1]),
                                    packh2(row[8], row[9]));
}

// ---------------- FC via fp16 mma.sync ----------------
#define FC_ITERS 8
#define ABUF 16384
#define BBUF 16384
#define FC_SMEM (2 * (ABUF + BBUF))   // 64 KB

__global__ __launch_bounds__(256, 2) void fc_mma_kernel(
    const float* __restrict__ bias, float* __restrict__ out)
{
    extern __shared__ char smem[];
    const uint32_t aBase = smem_u32(smem);
    const uint32_t bBase = aBase + 2 * ABUF;

    const int tid  = threadIdx.x;
    const int wid  = tid >> 5;
    const int lane = tid & 31;
    const int m0   = blockIdx.x * 128;     // fast dim: m-tiles share B via L2
    const int n0   = blockIdx.y * 128;

    const int mtW  = (wid >> 2) * 4;
    const int ntW  = (wid & 3) * 4;

    float acc[4][4][4];
#pragma unroll
    for (int mt = 0; mt < 4; mt++)
#pragma unroll
        for (int nt = 0; nt < 4; nt++)
#pragma unroll
            for (int r = 0; r < 4; r++) acc[mt][nt][r] = 0.0f;

    const int a_mtL  = tid >> 5;
    const int a_lane = tid & 31;
    const int b_ntL  = tid >> 4;
    const int b_in   = tid & 15;

#define LOAD_TILE(it, buf) do {                                                  \
    int _ks0 = (it) * 4;                                                         \
    const uint32_t* _ga = d_Af + (((size_t)(m0 / 16 + a_mtL) * KS16 + _ks0) * 128); \
    uint32_t _sa = aBase + (buf) * ABUF + (a_mtL * 4) * 512 + a_lane * 16;       \
    _Pragma("unroll")                                                            \
    for (int _c = 0; _c < 4; _c++)                                               \
        CP_ASYNC16(_sa + _c * 512, (const char*)(_ga + _c * 128 + a_lane * 4));  \
    const uint32_t* _gb = d_Bf + (((size_t)(n0 / 8 + b_ntL) * KS16 + _ks0) * 64); \
    uint32_t _sb = bBase + (buf) * BBUF + (b_ntL * 4) * 256 + b_in * 16;         \
    _Pragma("unroll")                                                            \
    for (int _c = 0; _c < 4; _c++)                                               \
        CP_ASYNC16(_sb + _c * 256, (const char*)(_gb + _c * 64 + b_in * 4));     \
} while (0)

    LOAD_TILE(0, 0);
    CP_COMMIT();

    for (int it = 0; it < FC_ITERS; it++) {
        const int buf = it & 1;
        if (it + 1 < FC_ITERS) LOAD_TILE(it + 1, buf ^ 1);
        CP_COMMIT();
        CP_WAIT1();
        __syncthreads();

        const uint32_t aOff = aBase + buf * ABUF;
        const uint32_t bOff = bBase + buf * BBUF;
#pragma unroll
        for (int ks = 0; ks < 4; ks++) {
            uint32_t a[4][4];
#pragma unroll
            for (int mt = 0; mt < 4; mt++) {
                uint32_t addr = aOff + ((mtW + mt) * 4 + ks) * 512 + lane * 16;
                asm volatile("ld.shared.v4.b32 {%0,%1,%2,%3}, [%4];"
                             : "=r"(a[mt][0]), "=r"(a[mt][1]),
                               "=r"(a[mt][2]), "=r"(a[mt][3]) : "r"(addr));
            }
            uint32_t b[4][2];
#pragma unroll
            for (int nt = 0; nt < 4; nt++) {
                uint32_t addr = bOff + ((ntW + nt) * 4 + ks) * 256 + lane * 8;
                asm volatile("ld.shared.v2.b32 {%0,%1}, [%2];"
                             : "=r"(b[nt][0]), "=r"(b[nt][1]) : "r"(addr));
            }
#pragma unroll
            for (int mt = 0; mt < 4; mt++)
#pragma unroll
                for (int nt = 0; nt < 4; nt++)
                    mma_f16(acc[mt][nt], a[mt], b[nt][0], b[nt][1]);
        }
        __syncthreads();
    }

    const int g   = lane >> 2;
    const int tig = lane & 3;
#pragma unroll
    for (int mt = 0; mt < 4; mt++) {
#pragma unroll
        for (int half = 0; half < 2; half++) {
            int m = m0 + (mtW + mt) * 16 + g + half * 8;
            if (m >= MROWS) continue;
            int bidx = m / TDEC;
            int tt   = m - bidx * TDEC;
            float* orow = out + ((size_t)bidx * 32 + tt + 1) * VOC;
#pragma unroll
            for (int nt = 0; nt < 4; nt++) {
                int n = n0 + (ntW + nt) * 8 + tig * 2;
                float b0 = __ldg(bias + n);
                float b1 = __ldg(bias + n + 1);
                float2 v = make_float2(acc[mt][nt][half * 2 + 0] + b0,
                                       acc[mt][nt][half * 2 + 1] + b1);
                *(float2*)(orow + n) = v;
            }
        }
    }
}

// ---------------- zero out[:, 0, :] ----------------
__global__ void zero_t0_kernel(float* __restrict__ out)
{
    int idx = blockIdx.x * blockDim.x + threadIdx.x;
    const int n4 = BATCH * (VOC / 4);
    if (idx < n4) {
        int b  = idx / (VOC / 4);
        int v4 = idx - b * (VOC / 4);
        ((float4*)(out + (size_t)b * 32 * VOC))[v4] = make_float4(0.f, 0.f, 0.f, 0.f);
    }
}

// ---------------- launch ----------------
extern "C" void kernel_launch(void* const* d_in, const int* in_sizes, int n_in,
                              void* d_out, int out_size)
{
    const int*   src     = (const int*)  d_in[0];
    const int*   tgt     = (const int*)  d_in[1];
    const float* enc_emb = (const float*)d_in[2];
    const float* dec_emb = (const float*)d_in[3];
    const float* enc_Wih = (const float*)d_in[4];
    const float* enc_Whh = (const float*)d_in[5];
    const float* enc_bih = (const float*)d_in[6];
    const float* enc_bhh = (const float*)d_in[7];
    const float* dec_Wih = (const float*)d_in[8];
    const float* dec_Whh = (const float*)d_in[9];
    const float* dec_bih = (const float*)d_in[10];
    const float* dec_bhh = (const float*)d_in[11];
    const float* fc_W    = (const float*)d_in[12];
    const float* fc_b    = (const float*)d_in[13];
    float* out = (float*)d_out;

    static int attr_set = 0;
    if (!attr_set) {
        cudaFuncSetAttribute(fc_mma_kernel,
                             cudaFuncAttributeMaxDynamicSharedMemorySize, FC_SMEM);
        cudaFuncSetAttribute(scan_tc_kernel,
                             cudaFuncAttributeMaxDynamicSharedMemorySize, SCAN_SMEM);
        cudaFuncSetAttribute(xp_mma_kernel,
                             cudaFuncAttributeMaxDynamicSharedMemorySize, XP_SMEM);
        attr_set = 1;
    }

    convWih_frag_kernel<<<(2 * 256 * EKS16 * 32 + 255) / 256, 256>>>(enc_Wih, dec_Wih);   // 1
    xp_mma_kernel<<<dim3(16, SENC + TDEC), 256, XP_SMEM>>>(
        src, tgt, enc_emb, dec_emb, enc_bih, enc_bhh, dec_bih, dec_bhh);                  // 2
    convWhh_frag_kernel<<<(2 * SNBLK * 4 * KS16 * 32 + 255) / 256, 256>>>(enc_Whh, dec_Whh); // 3 (+ ctr reset)
    scan_tc_kernel<<<SNBLK, 256, SCAN_SMEM>>>();                                          // 4 <- ncu window
    convB_frag_kernel<<<(NT8 * KS16 * 32 + 255) / 256, 256>>>(fc_W);                      // 5
    convA_frag_kernel<<<((MPAD / 16) * KS16 * 32 + 255) / 256, 256>>>();                  // 6
    zero_t0_kernel<<<(BATCH * (VOC / 4) + 255) / 256, 256>>>(out);                        // 7
    fc_mma_kernel<<<dim3(MPAD / 128, VOC / 128), 256, FC_SMEM>>>(fc_b, out);              // 8
}